// round 3
// baseline (speedup 1.0000x reference)
#include <cuda_runtime.h>
#include <math.h>

#define NB      2
#define LQ      12240
#define DIM     256
#define HEADS   8
#define LEVELS  4
#define POINTS  4
#define HD      32
#define MROWS   (NB * LQ)   // 24480

// Scratch (allocation-free requirement -> __device__ globals)
__device__ float g_value  [MROWS * DIM];
__device__ float g_off    [MROWS * DIM];
__device__ float g_attn   [MROWS * HEADS * 16];
__device__ float g_attout [MROWS * DIM];
__device__ float g_out2   [MROWS * DIM];

typedef unsigned long long u64;

__device__ __forceinline__ u64 ffma2(u64 a, u64 b, u64 c) {
    u64 d;
    asm("fma.rn.f32x2 %0, %1, %2, %3;" : "=l"(d) : "l"(a), "l"(b), "l"(c));
    return d;
}

// ---------------------------------------------------------------------------
// GEMM: C[M,N] = A[M,K] * B[K,N] + bias[N], fp32, packed f32x2 FMA
// BM=128, BN=128, BK=16, 256 threads, 8x8 micro-tile (as 8 rows x 4 f32x2 pairs)
// A smem tile stored DUPLICATED: As2[k][2r]=As2[k][2r+1]=A[r][k], so LDS.128
// yields ready (a,a) f32x2 operands with zero pack movs.
// ---------------------------------------------------------------------------
#define BM 128
#define BN 128
#define BK 16
#define AS_STRIDE (2*BM + 4)   // 260 floats, 1040B: 16B-aligned rows
#define BS_STRIDE (BN + 4)     // 132 floats,  528B: 16B-aligned rows

__global__ __launch_bounds__(256, 2) void gemm_bias_kernel(
    const float* __restrict__ A, const float* __restrict__ B,
    const float* __restrict__ bias, float* __restrict__ C,
    int M, int N, int K)
{
    __shared__ float As2[BK][AS_STRIDE];
    __shared__ float Bs [BK][BS_STRIDE];

    const int tid = threadIdx.x;
    const int tx = tid & 15;          // 0..15 (N dir)
    const int ty = tid >> 4;          // 0..15 (M dir)
    const int bm = blockIdx.y * BM;
    const int bn = blockIdx.x * BN;

    // A load: thread -> one row, 8 consecutive cols (2 float4)
    const int a_row = tid >> 1;              // 0..127
    const int a_col = (tid & 1) * 8;         // 0 or 8
    // B load: thread -> 2 rows (r, r+8), one float4 each
    const int b_row = tid >> 5;              // 0..7
    const int b_col = (tid & 31) * 4;        // 0..124

    u64 acc[8][4];
#pragma unroll
    for (int i = 0; i < 8; i++)
#pragma unroll
        for (int j = 0; j < 4; j++) acc[i][j] = 0ull;

    const bool a_valid = (bm + a_row) < M;

    for (int kk = 0; kk < K; kk += BK) {
        float4 va0 = make_float4(0.f,0.f,0.f,0.f), va1 = va0;
        if (a_valid) {
            const float* ap = &A[(size_t)(bm + a_row) * K + kk + a_col];
            va0 = *(const float4*)(ap);
            va1 = *(const float4*)(ap + 4);
        }
        {
            float av[8] = {va0.x, va0.y, va0.z, va0.w, va1.x, va1.y, va1.z, va1.w};
#pragma unroll
            for (int j = 0; j < 8; j++) {
                float2 d = make_float2(av[j], av[j]);
                *(float2*)&As2[a_col + j][2 * a_row] = d;   // duplicated pair
            }
        }
        {
            float4 vb0 = *(const float4*)&B[(size_t)(kk + b_row) * N + bn + b_col];
            float4 vb1 = *(const float4*)&B[(size_t)(kk + b_row + 8) * N + bn + b_col];
            *(float4*)&Bs[b_row][b_col]     = vb0;
            *(float4*)&Bs[b_row + 8][b_col] = vb1;
        }
        __syncthreads();

#pragma unroll
        for (int k = 0; k < BK; k++) {
            // 8 duplicated A pairs for rows ty*8..ty*8+7 : 4 x LDS.128
            ulonglong2 a01 = *(const ulonglong2*)&As2[k][ty * 16 + 0];
            ulonglong2 a23 = *(const ulonglong2*)&As2[k][ty * 16 + 4];
            ulonglong2 a45 = *(const ulonglong2*)&As2[k][ty * 16 + 8];
            ulonglong2 a67 = *(const ulonglong2*)&As2[k][ty * 16 + 12];
            // 4 B pairs for cols tx*8..tx*8+7 : 2 x LDS.128
            ulonglong2 b01 = *(const ulonglong2*)&Bs[k][tx * 8];
            ulonglong2 b23 = *(const ulonglong2*)&Bs[k][tx * 8 + 4];
            u64 ar[8] = {a01.x, a01.y, a23.x, a23.y, a45.x, a45.y, a67.x, a67.y};
            u64 br[4] = {b01.x, b01.y, b23.x, b23.y};
#pragma unroll
            for (int i = 0; i < 8; i++)
#pragma unroll
                for (int j = 0; j < 4; j++)
                    acc[i][j] = ffma2(ar[i], br[j], acc[i][j]);
        }
        __syncthreads();
    }

    float4 bv0 = *(const float4*)&bias[bn + tx * 8];
    float4 bv1 = *(const float4*)&bias[bn + tx * 8 + 4];
#pragma unroll
    for (int i = 0; i < 8; i++) {
        int row = bm + ty * 8 + i;
        if (row < M) {
            float2 p0 = *(float2*)&acc[i][0];
            float2 p1 = *(float2*)&acc[i][1];
            float2 p2 = *(float2*)&acc[i][2];
            float2 p3 = *(float2*)&acc[i][3];
            float4 o0 = make_float4(p0.x + bv0.x, p0.y + bv0.y, p1.x + bv0.z, p1.y + bv0.w);
            float4 o1 = make_float4(p2.x + bv1.x, p2.y + bv1.y, p3.x + bv1.z, p3.y + bv1.w);
            float* cp = &C[(size_t)row * N + bn + tx * 8];
            *(float4*)(cp)     = o0;
            *(float4*)(cp + 4) = o1;
        }
    }
}

// ---------------------------------------------------------------------------
// Deformable sampling: warp == (query, head); lane p(=lane&15) preps point p,
// gather phase broadcasts via shfl. Validity folded into weights (zeroed),
// indices clamped -> unconditional loads.
// ---------------------------------------------------------------------------
__global__ __launch_bounds__(256) void sample_kernel(
    const float* __restrict__ value,
    const float* __restrict__ off,
    const float* __restrict__ logits,
    const float* __restrict__ ref,
    float* __restrict__ out)
{
    const unsigned FULL = 0xffffffffu;
    const int qg   = blockIdx.x;            // 0..MROWS-1
    const int n    = qg / LQ;
    const int h    = threadIdx.x >> 5;
    const int lane = threadIdx.x & 31;
    const int p    = lane & 15;              // point id (dup in upper half-warp)
    const int l    = p >> 2;                 // level

    // --- softmax over 16 logits (each lane owns one; xor-reduce within 16) ---
    float lg = logits[(size_t)qg * (HEADS * 16) + h * 16 + p];
    float mx = lg;
#pragma unroll
    for (int o = 8; o > 0; o >>= 1)
        mx = fmaxf(mx, __shfl_xor_sync(FULL, mx, o));
    float e = __expf(lg - mx);
    float sum = e;
#pragma unroll
    for (int o = 8; o > 0; o >>= 1)
        sum += __shfl_xor_sync(FULL, sum, o);
    const float aw = __fdividef(e, sum);

    // --- per-point bilinear prep (lane p) ---
    const int W  = 96 >> l;                        // H == W per level
    const int S0 = 12288 - 3 * (4096 >> (2 * l));  // level start row
    const float rx = ref[(size_t)qg * (LEVELS * 2) + l * 2 + 0] * (float)W;
    const float ry = ref[(size_t)qg * (LEVELS * 2) + l * 2 + 1] * (float)W;
    const float ox = off[(size_t)qg * DIM + h * 32 + p * 2 + 0];
    const float oy = off[(size_t)qg * DIM + h * 32 + p * 2 + 1];
    const float x = rx + ox - 0.5f;
    const float y = ry + oy - 0.5f;
    const float x0f = floorf(x), y0f = floorf(y);
    const int x0 = (int)x0f, y0 = (int)y0f;
    const float fx = x - x0f, fy = y - y0f;

    const float vx0 = (x0 >= 0 && x0 < W) ? 1.f : 0.f;
    const float vx1 = (x0 + 1 >= 0 && x0 + 1 < W) ? 1.f : 0.f;
    const float vy0 = (y0 >= 0 && y0 < W) ? 1.f : 0.f;
    const float vy1 = (y0 + 1 >= 0 && y0 + 1 < W) ? 1.f : 0.f;
    const float wx0 = (1.f - fx) * vx0;
    const float wx1 = fx * vx1;
    const float wy0 = (1.f - fy) * aw * vy0;
    const float wy1 = fy * aw * vy1;
    float w00 = wx0 * wy0, w01 = wx1 * wy0, w10 = wx0 * wy1, w11 = wx1 * wy1;
    int c0 = min(max(x0, 0), W - 1) * DIM;
    int c1 = min(max(x0 + 1, 0), W - 1) * DIM;
    int r0 = (S0 + min(max(y0, 0), W - 1) * W) * DIM;
    int r1 = (S0 + min(max(y0 + 1, 0), W - 1) * W) * DIM;

    // --- gather: lane == channel ---
    const float* vb = value + (size_t)n * (LQ * DIM) + h * HD + lane;
    float acc = 0.f;
#pragma unroll
    for (int q = 0; q < 16; q++) {
        const float u00 = __shfl_sync(FULL, w00, q);
        const float u01 = __shfl_sync(FULL, w01, q);
        const float u10 = __shfl_sync(FULL, w10, q);
        const float u11 = __shfl_sync(FULL, w11, q);
        const int a0 = __shfl_sync(FULL, r0, q);
        const int a1 = __shfl_sync(FULL, r1, q);
        const int b0 = __shfl_sync(FULL, c0, q);
        const int b1 = __shfl_sync(FULL, c1, q);
        acc = fmaf(u00, vb[a0 + b0], acc);
        acc = fmaf(u01, vb[a0 + b1], acc);
        acc = fmaf(u10, vb[a1 + b0], acc);
        acc = fmaf(u11, vb[a1 + b1], acc);
    }
    out[(size_t)qg * DIM + h * HD + lane] = acc;
}

// ---------------------------------------------------------------------------
// Residual + LayerNorm: 1 block per row (256 threads == DIM)
// ---------------------------------------------------------------------------
__global__ __launch_bounds__(256) void ln_kernel(
    const float* __restrict__ src, const float* __restrict__ y,
    const float* __restrict__ gamma, const float* __restrict__ beta,
    float* __restrict__ out)
{
    const int row = blockIdx.x;
    const int t = threadIdx.x;
    const size_t idx = (size_t)row * DIM + t;
    const float x = src[idx] + y[idx];

    float s = x, s2 = x * x;
#pragma unroll
    for (int o = 16; o > 0; o >>= 1) {
        s  += __shfl_down_sync(0xffffffffu, s, o);
        s2 += __shfl_down_sync(0xffffffffu, s2, o);
    }
    __shared__ float ss[8], ss2[8];
    const int w = t >> 5;
    if ((t & 31) == 0) { ss[w] = s; ss2[w] = s2; }
    __syncthreads();
    float sum = 0.f, sum2 = 0.f;
#pragma unroll
    for (int i = 0; i < 8; i++) { sum += ss[i]; sum2 += ss2[i]; }

    const float mu  = sum * (1.0f / DIM);
    const float var = sum2 * (1.0f / DIM) - mu * mu;
    const float r = rsqrtf(var + 1e-5f);
    out[idx] = (x - mu) * r * gamma[t] + beta[t];
}

// ---------------------------------------------------------------------------
extern "C" void kernel_launch(void* const* d_in, const int* in_sizes, int n_in,
                              void* d_out, int out_size)
{
    const float* src    = (const float*)d_in[0];
    const float* refpts = (const float*)d_in[1];
    const float* w_value = (const float*)d_in[4];
    const float* b_value = (const float*)d_in[5];
    const float* w_off   = (const float*)d_in[6];
    const float* b_off   = (const float*)d_in[7];
    const float* w_attn  = (const float*)d_in[8];
    const float* b_attn  = (const float*)d_in[9];
    const float* w_out   = (const float*)d_in[10];
    const float* b_out   = (const float*)d_in[11];
    const float* gamma   = (const float*)d_in[12];
    const float* beta    = (const float*)d_in[13];
    float* out = (float*)d_out;

    float *gv, *go, *ga, *gao, *g2;
    cudaGetSymbolAddress((void**)&gv,  g_value);
    cudaGetSymbolAddress((void**)&go,  g_off);
    cudaGetSymbolAddress((void**)&ga,  g_attn);
    cudaGetSymbolAddress((void**)&gao, g_attout);
    cudaGetSymbolAddress((void**)&g2,  g_out2);

    const int M = MROWS, K = DIM;
    dim3 blk(256);
    const int gy = (M + BM - 1) / BM;   // 192

    gemm_bias_kernel<<<dim3(256 / BN, gy), blk>>>(src, w_value, b_value, gv, M, 256, K);
    gemm_bias_kernel<<<dim3(256 / BN, gy), blk>>>(src, w_off,   b_off,   go, M, 256, K);
    gemm_bias_kernel<<<dim3(128 / BN, gy), blk>>>(src, w_attn,  b_attn,  ga, M, 128, K);

    sample_kernel<<<MROWS, blk>>>(gv, go, ga, refpts, gao);

    gemm_bias_kernel<<<dim3(256 / BN, gy), blk>>>(gao, w_out, b_out, g2, M, 256, K);

    ln_kernel<<<MROWS, blk>>>(src, g2, gamma, beta, out);
}

// round 5
// speedup vs baseline: 1.7974x; 1.7974x over previous
#include <cuda_runtime.h>
#include <cuda_bf16.h>
#include <cstdint>
#include <math.h>

#define NB      2
#define LQ      12240
#define DIM     256
#define HEADS   8
#define LEVELS  4
#define POINTS  4
#define HD      32
#define MROWS   (NB * LQ)   // 24480

// ------------------------- scratch (no allocs allowed) ----------------------
__device__ float g_value  [MROWS * DIM];
__device__ float g_off    [MROWS * DIM];
__device__ float g_attn   [MROWS * HEADS * 16];
__device__ float g_attout [MROWS * DIM];
__device__ float g_out2   [MROWS * DIM];

// bf16 split operands
__device__ __nv_bfloat16 g_ah[MROWS * DIM];
__device__ __nv_bfloat16 g_al[MROWS * DIM];
// concatenated transposed+split weights [n][k] K-major:
// rows 0-255 value, 256-511 off, 512-639 attn, 640-895 out
__device__ __nv_bfloat16 g_btc_h[896 * 256];
__device__ __nv_bfloat16 g_btc_l[896 * 256];

// ------------------------------ PTX helpers ---------------------------------
__device__ __forceinline__ uint32_t smem_u32(const void* p) {
    uint32_t a;
    asm("{ .reg .u64 t; cvta.to.shared.u64 t, %1; cvt.u32.u64 %0, t; }" : "=r"(a) : "l"(p));
    return a;
}
__device__ __forceinline__ void cpa16(uint32_t dst, const void* src, bool v) {
    asm volatile("cp.async.cg.shared.global [%0], [%1], 16, %2;"
        :: "r"(dst), "l"(src), "r"(v ? 16 : 0) : "memory");
}
__device__ __forceinline__ void ldsm_x4(uint32_t addr, uint32_t* r) {
    asm volatile("ldmatrix.sync.aligned.m8n8.x4.shared.b16 {%0,%1,%2,%3}, [%4];"
        : "=r"(r[0]), "=r"(r[1]), "=r"(r[2]), "=r"(r[3]) : "r"(addr));
}
__device__ __forceinline__ void mma_bf16(float* c, const uint32_t* a, const uint32_t* b) {
    asm volatile("mma.sync.aligned.m16n8k16.row.col.f32.bf16.bf16.f32 "
        "{%0,%1,%2,%3}, {%4,%5,%6,%7}, {%8,%9}, {%0,%1,%2,%3};"
        : "+f"(c[0]), "+f"(c[1]), "+f"(c[2]), "+f"(c[3])
        : "r"(a[0]), "r"(a[1]), "r"(a[2]), "r"(a[3]), "r"(b[0]), "r"(b[1]));
}

// ---------------------------------------------------------------------------
// fp32 -> bf16 hi/lo split (A operand), vectorized by 4
// ---------------------------------------------------------------------------
__global__ __launch_bounds__(256) void split_a_kernel(
    const float* __restrict__ A, __nv_bfloat16* __restrict__ Ah,
    __nv_bfloat16* __restrict__ Al, int n4)
{
    int i = blockIdx.x * 256 + threadIdx.x;
    if (i >= n4) return;
    float4 a = ((const float4*)A)[i];
    __nv_bfloat16 h0 = __float2bfloat16_rn(a.x);
    __nv_bfloat16 h1 = __float2bfloat16_rn(a.y);
    __nv_bfloat16 h2 = __float2bfloat16_rn(a.z);
    __nv_bfloat16 h3 = __float2bfloat16_rn(a.w);
    __nv_bfloat16 l0 = __float2bfloat16_rn(a.x - __bfloat162float(h0));
    __nv_bfloat16 l1 = __float2bfloat16_rn(a.y - __bfloat162float(h1));
    __nv_bfloat16 l2 = __float2bfloat16_rn(a.z - __bfloat162float(h2));
    __nv_bfloat16 l3 = __float2bfloat16_rn(a.w - __bfloat162float(h3));
    ((__nv_bfloat162*)Ah)[2 * i + 0] = __nv_bfloat162(h0, h1);
    ((__nv_bfloat162*)Ah)[2 * i + 1] = __nv_bfloat162(h2, h3);
    ((__nv_bfloat162*)Al)[2 * i + 0] = __nv_bfloat162(l0, l1);
    ((__nv_bfloat162*)Al)[2 * i + 1] = __nv_bfloat162(l2, l3);
}

// B [K=256, Nc] row-major fp32 -> Bt [rowoff+n][k] bf16 hi/lo
__global__ __launch_bounds__(256) void split_bt_kernel(
    const float* __restrict__ B, __nv_bfloat16* __restrict__ Bh,
    __nv_bfloat16* __restrict__ Bl, int Nc, int rowoff)
{
    int idx = blockIdx.x * 256 + threadIdx.x;
    if (idx >= 256 * Nc) return;
    int k = idx / Nc, n = idx - k * Nc;
    float b = B[idx];
    __nv_bfloat16 h = __float2bfloat16_rn(b);
    __nv_bfloat16 l = __float2bfloat16_rn(b - __bfloat162float(h));
    Bh[(size_t)(rowoff + n) * 256 + k] = h;
    Bl[(size_t)(rowoff + n) * 256 + k] = l;
}

// ---------------------------------------------------------------------------
// Tensor-core GEMM via mma.sync bf16, 3-term split, cp.async double buffer.
// CTA tile 128x128, K=256 (8 chunks of 32). 8 warps = 4(M) x 2(N), warp 32x64.
// smem halves layout, row pad 40 (80B) -> conflict-free ldmatrix.
// fused=1: blockIdx.y 0-1 -> C0 (stride 256), 2-3 -> C1 (256), 4 -> C2 (128)
// ---------------------------------------------------------------------------
#define PADK 40
#define SM_AH 0
#define SM_AL 10240
#define SM_BH 20480
#define SM_BL 30720
#define SMEM_BYTES (40960 * 2)

__global__ __launch_bounds__(256) void gemm_mma_kernel(
    const __nv_bfloat16* __restrict__ Ah, const __nv_bfloat16* __restrict__ Al,
    const __nv_bfloat16* __restrict__ Bth, const __nv_bfloat16* __restrict__ Btl,
    float* C0, float* C1, float* C2,
    const float* b0, const float* b1, const float* b2,
    int M, int fused)
{
    extern __shared__ __align__(16) char smem[];
    const uint32_t sbase = smem_u32(smem);

    const int tid  = threadIdx.x;
    const int lane = tid & 31;
    const int wid  = tid >> 5;
    const int wm   = wid & 3;
    const int wn   = wid >> 2;
    const int bm   = blockIdx.x * 128;
    const int bn   = blockIdx.y * 128;

    float* Cp; const float* bp; int stride, coloff;
    if (fused) {
        if (blockIdx.y < 2)      { Cp = C0; bp = b0; stride = 256; coloff = bn; }
        else if (blockIdx.y < 4) { Cp = C1; bp = b1; stride = 256; coloff = bn - 256; }
        else                     { Cp = C2; bp = b2; stride = 128; coloff = 0; }
    } else { Cp = C0; bp = b0; stride = 256; coloff = bn; }

    float acc[2][8][4];
#pragma unroll
    for (int i = 0; i < 2; i++)
#pragma unroll
        for (int j = 0; j < 8; j++)
#pragma unroll
            for (int t = 0; t < 4; t++) acc[i][j][t] = 0.f;

    // ---- cp.async chunk loader ----
    auto load_chunk = [&](int kk, int buf) {
        const uint32_t ab = buf * 5120;  // halves
#pragma unroll
        for (int t = 0; t < 2; t++) {
            int idx = tid + 256 * t;
            int row = idx >> 2, seg = idx & 3;
            uint32_t d = (uint32_t)(row * PADK + seg * 8) * 2;
            bool va = (bm + row) < M;
            const __nv_bfloat16* sah = Ah + (size_t)(bm + row) * 256 + kk * 32 + seg * 8;
            const __nv_bfloat16* sal = Al + (size_t)(bm + row) * 256 + kk * 32 + seg * 8;
            cpa16(sbase + (SM_AH + ab) * 2 + d, sah, va);
            cpa16(sbase + (SM_AL + ab) * 2 + d, sal, va);
            const __nv_bfloat16* sbh = Bth + (size_t)(bn + row) * 256 + kk * 32 + seg * 8;
            const __nv_bfloat16* sbl = Btl + (size_t)(bn + row) * 256 + kk * 32 + seg * 8;
            cpa16(sbase + (SM_BH + ab) * 2 + d, sbh, true);
            cpa16(sbase + (SM_BL + ab) * 2 + d, sbl, true);
        }
        asm volatile("cp.async.commit_group;" ::: "memory");
    };

    load_chunk(0, 0);

    for (int kk = 0; kk < 8; kk++) {
        asm volatile("cp.async.wait_group 0;" ::: "memory");
        __syncthreads();
        if (kk < 7) load_chunk(kk + 1, (kk + 1) & 1);

        const uint32_t ab = (kk & 1) * 5120;
#pragma unroll
        for (int ks = 0; ks < 2; ks++) {
            uint32_t ah[2][4], alr[2][4];
#pragma unroll
            for (int mt = 0; mt < 2; mt++) {
                int row = wm * 32 + mt * 16 + (lane & 15);
                int col = ks * 16 + (lane >> 4) * 8;
                ldsm_x4(sbase + (uint32_t)(SM_AH + ab + row * PADK + col) * 2, ah[mt]);
                ldsm_x4(sbase + (uint32_t)(SM_AL + ab + row * PADK + col) * 2, alr[mt]);
            }
#pragma unroll
            for (int q = 0; q < 4; q++) {
                int rowB = wn * 64 + q * 16 + (lane & 7) + ((lane >> 4) & 1) * 8;
                int colB = ((lane >> 3) & 1) * 8 + ks * 16;
                uint32_t bh[4], bl[4];
                ldsm_x4(sbase + (uint32_t)(SM_BH + ab + rowB * PADK + colB) * 2, bh);
                ldsm_x4(sbase + (uint32_t)(SM_BL + ab + rowB * PADK + colB) * 2, bl);
#pragma unroll
                for (int mt = 0; mt < 2; mt++) {
                    mma_bf16(acc[mt][2 * q + 0], ah[mt], bh + 0);
                    mma_bf16(acc[mt][2 * q + 1], ah[mt], bh + 2);
                    mma_bf16(acc[mt][2 * q + 0], ah[mt], bl + 0);
                    mma_bf16(acc[mt][2 * q + 1], ah[mt], bl + 2);
                    mma_bf16(acc[mt][2 * q + 0], alr[mt], bh + 0);
                    mma_bf16(acc[mt][2 * q + 1], alr[mt], bh + 2);
                }
            }
        }
        __syncthreads();
    }

    // ---- epilogue: bias + store ----
#pragma unroll
    for (int mt = 0; mt < 2; mt++) {
        int r0 = bm + wm * 32 + mt * 16 + (lane >> 2);
        int r1 = r0 + 8;
#pragma unroll
        for (int nt = 0; nt < 8; nt++) {
            int c = coloff + wn * 64 + nt * 8 + 2 * (lane & 3);
            float bb0 = bp[c], bb1 = bp[c + 1];
            if (r0 < M) {
                float2 v = make_float2(acc[mt][nt][0] + bb0, acc[mt][nt][1] + bb1);
                *(float2*)&Cp[(size_t)r0 * stride + c] = v;
            }
            if (r1 < M) {
                float2 v = make_float2(acc[mt][nt][2] + bb0, acc[mt][nt][3] + bb1);
                *(float2*)&Cp[(size_t)r1 * stride + c] = v;
            }
        }
    }
}

// ---------------------------------------------------------------------------
// Deformable sampling: warp == (query, head); lane p preps point p, gather
// broadcasts combined addresses + weights via shfl; dual accumulators.
// ---------------------------------------------------------------------------
__global__ __launch_bounds__(256) void sample_kernel(
    const float* __restrict__ value,
    const float* __restrict__ off,
    const float* __restrict__ logits,
    const float* __restrict__ ref,
    float* __restrict__ out)
{
    const unsigned FULL = 0xffffffffu;
    const int qg   = blockIdx.x;
    const int n    = qg / LQ;
    const int h    = threadIdx.x >> 5;
    const int lane = threadIdx.x & 31;
    const int p    = lane & 15;
    const int l    = p >> 2;

    float lg = logits[(size_t)qg * (HEADS * 16) + h * 16 + p];
    float mx = lg;
#pragma unroll
    for (int o = 8; o > 0; o >>= 1) mx = fmaxf(mx, __shfl_xor_sync(FULL, mx, o));
    float e = __expf(lg - mx);
    float sum = e;
#pragma unroll
    for (int o = 8; o > 0; o >>= 1) sum += __shfl_xor_sync(FULL, sum, o);
    const float aw = __fdividef(e, sum);

    const int W  = 96 >> l;
    const int S0 = 12288 - 3 * (4096 >> (2 * l));
    const float rx = ref[(size_t)qg * (LEVELS * 2) + l * 2 + 0] * (float)W;
    const float ry = ref[(size_t)qg * (LEVELS * 2) + l * 2 + 1] * (float)W;
    const float ox = off[(size_t)qg * DIM + h * 32 + p * 2 + 0];
    const float oy = off[(size_t)qg * DIM + h * 32 + p * 2 + 1];
    const float x = rx + ox - 0.5f;
    const float y = ry + oy - 0.5f;
    const float x0f = floorf(x), y0f = floorf(y);
    const int x0 = (int)x0f, y0 = (int)y0f;
    const float fx = x - x0f, fy = y - y0f;

    const float vx0 = (x0 >= 0 && x0 < W) ? 1.f : 0.f;
    const float vx1 = (x0 + 1 >= 0 && x0 + 1 < W) ? 1.f : 0.f;
    const float vy0 = (y0 >= 0 && y0 < W) ? 1.f : 0.f;
    const float vy1 = (y0 + 1 >= 0 && y0 + 1 < W) ? 1.f : 0.f;
    const float wx0 = (1.f - fx) * vx0;
    const float wx1 = fx * vx1;
    const float wy0 = (1.f - fy) * aw * vy0;
    const float wy1 = fy * aw * vy1;
    float w00 = wx0 * wy0, w01 = wx1 * wy0, w10 = wx0 * wy1, w11 = wx1 * wy1;
    int c0 = min(max(x0, 0), W - 1) * DIM;
    int c1 = min(max(x0 + 1, 0), W - 1) * DIM;
    int r0 = (S0 + min(max(y0, 0), W - 1) * W) * DIM;
    int r1 = (S0 + min(max(y0 + 1, 0), W - 1) * W) * DIM;
    int i00 = r0 + c0, i01 = r0 + c1, i10 = r1 + c0, i11 = r1 + c1;

    const float* vb = value + (size_t)n * (LQ * DIM) + h * HD + lane;
    float acc0 = 0.f, acc1 = 0.f;
#pragma unroll
    for (int q = 0; q < 16; q++) {
        const int a00 = __shfl_sync(FULL, i00, q);
        const int a01 = __shfl_sync(FULL, i01, q);
        const int a10 = __shfl_sync(FULL, i10, q);
        const int a11 = __shfl_sync(FULL, i11, q);
        const float u00 = __shfl_sync(FULL, w00, q);
        const float u01 = __shfl_sync(FULL, w01, q);
        const float u10 = __shfl_sync(FULL, w10, q);
        const float u11 = __shfl_sync(FULL, w11, q);
        const float v00 = vb[a00];
        const float v01 = vb[a01];
        const float v10 = vb[a10];
        const float v11 = vb[a11];
        acc0 = fmaf(u00, v00, acc0);
        acc1 = fmaf(u01, v01, acc1);
        acc0 = fmaf(u10, v10, acc0);
        acc1 = fmaf(u11, v11, acc1);
    }
    out[(size_t)qg * DIM + h * HD + lane] = acc0 + acc1;
}

// ---------------------------------------------------------------------------
// Residual + LayerNorm
// ---------------------------------------------------------------------------
__global__ __launch_bounds__(256) void ln_kernel(
    const float* __restrict__ src, const float* __restrict__ y,
    const float* __restrict__ gamma, const float* __restrict__ beta,
    float* __restrict__ out)
{
    const int row = blockIdx.x;
    const int t = threadIdx.x;
    const size_t idx = (size_t)row * DIM + t;
    const float x = src[idx] + y[idx];

    float s = x, s2 = x * x;
#pragma unroll
    for (int o = 16; o > 0; o >>= 1) {
        s  += __shfl_down_sync(0xffffffffu, s, o);
        s2 += __shfl_down_sync(0xffffffffu, s2, o);
    }
    __shared__ float ss[8], ss2[8];
    const int w = t >> 5;
    if ((t & 31) == 0) { ss[w] = s; ss2[w] = s2; }
    __syncthreads();
    float sum = 0.f, sum2 = 0.f;
#pragma unroll
    for (int i = 0; i < 8; i++) { sum += ss[i]; sum2 += ss2[i]; }

    const float mu  = sum * (1.0f / DIM);
    const float var = sum2 * (1.0f / DIM) - mu * mu;
    const float r = rsqrtf(var + 1e-5f);
    out[idx] = (x - mu) * r * gamma[t] + beta[t];
}

// ---------------------------------------------------------------------------
extern "C" void kernel_launch(void* const* d_in, const int* in_sizes, int n_in,
                              void* d_out, int out_size)
{
    const float* src    = (const float*)d_in[0];
    const float* refpts = (const float*)d_in[1];
    const float* w_value = (const float*)d_in[4];
    const float* b_value = (const float*)d_in[5];
    const float* w_off   = (const float*)d_in[6];
    const float* b_off   = (const float*)d_in[7];
    const float* w_attn  = (const float*)d_in[8];
    const float* b_attn  = (const float*)d_in[9];
    const float* w_out   = (const float*)d_in[10];
    const float* b_out   = (const float*)d_in[11];
    const float* gamma   = (const float*)d_in[12];
    const float* beta    = (const float*)d_in[13];
    float* out = (float*)d_out;

    float *gv, *go, *ga, *gao, *g2;
    cudaGetSymbolAddress((void**)&gv,  g_value);
    cudaGetSymbolAddress((void**)&go,  g_off);
    cudaGetSymbolAddress((void**)&ga,  g_attn);
    cudaGetSymbolAddress((void**)&gao, g_attout);
    cudaGetSymbolAddress((void**)&g2,  g_out2);
    __nv_bfloat16 *ah, *al, *bch, *bcl;
    cudaGetSymbolAddress((void**)&ah,  g_ah);
    cudaGetSymbolAddress((void**)&al,  g_al);
    cudaGetSymbolAddress((void**)&bch, g_btc_h);
    cudaGetSymbolAddress((void**)&bcl, g_btc_l);

    const int M = MROWS;
    cudaFuncSetAttribute(gemm_mma_kernel, cudaFuncAttributeMaxDynamicSharedMemorySize, SMEM_BYTES);

    dim3 blk(256);
    const int n4 = M * DIM / 4;
    const int gtiles = (M + 127) / 128;   // 192

    // weight split/transpose into concat buffer (tiny)
    split_bt_kernel<<<(256 * 256 + 255) / 256, blk>>>(w_value, bch, bcl, 256, 0);
    split_bt_kernel<<<(256 * 256 + 255) / 256, blk>>>(w_off,   bch, bcl, 256, 256);
    split_bt_kernel<<<(256 * 128 + 255) / 256, blk>>>(w_attn,  bch, bcl, 128, 512);
    split_bt_kernel<<<(256 * 256 + 255) / 256, blk>>>(w_out,   bch, bcl, 256, 640);

    // src split
    split_a_kernel<<<(n4 + 255) / 256, blk>>>(src, ah, al, n4);

    // fused input projections: N=640 (value 256 | off 256 | attn 128)
    gemm_mma_kernel<<<dim3(gtiles, 5), blk, SMEM_BYTES>>>(
        ah, al, bch, bcl, gv, go, ga, b_value, b_off, b_attn, M, 1);

    // deformable sampling
    sample_kernel<<<MROWS, blk>>>(gv, go, ga, refpts, gao);

    // output projection
    split_a_kernel<<<(n4 + 255) / 256, blk>>>(gao, ah, al, n4);
    gemm_mma_kernel<<<dim3(gtiles, 2), blk, SMEM_BYTES>>>(
        ah, al, bch + 640 * 256, bcl + 640 * 256, g2, nullptr, nullptr,
        b_out, nullptr, nullptr, M, 0);

    // residual + layernorm
    ln_kernel<<<MROWS, blk>>>(src, g2, gamma, beta, out);
}

// round 6
// speedup vs baseline: 2.2836x; 1.2706x over previous
#include <cuda_runtime.h>
#include <cuda_bf16.h>
#include <cstdint>
#include <math.h>

#define NB      2
#define LQ      12240
#define DIM     256
#define HEADS   8
#define LEVELS  4
#define POINTS  4
#define HD      32
#define MROWS   (NB * LQ)   // 24480

// ------------------------- scratch (no allocs allowed) ----------------------
__device__ float g_value  [MROWS * DIM];
__device__ float g_off    [MROWS * DIM];
__device__ float g_attn   [MROWS * HEADS * 16];
__device__ float g_out2   [MROWS * DIM];

// bf16 split operands
__device__ __nv_bfloat16 g_ah[MROWS * DIM];
__device__ __nv_bfloat16 g_al[MROWS * DIM];
// concatenated transposed+split weights [n][k] K-major:
// rows 0-255 value, 256-511 off, 512-639 attn, 640-895 out
__device__ __nv_bfloat16 g_btc_h[896 * 256];
__device__ __nv_bfloat16 g_btc_l[896 * 256];

// ------------------------------ PTX helpers ---------------------------------
__device__ __forceinline__ uint32_t smem_u32(const void* p) {
    uint32_t a;
    asm("{ .reg .u64 t; cvta.to.shared.u64 t, %1; cvt.u32.u64 %0, t; }" : "=r"(a) : "l"(p));
    return a;
}
__device__ __forceinline__ void cpa16(uint32_t dst, const void* src, bool v) {
    asm volatile("cp.async.cg.shared.global [%0], [%1], 16, %2;"
        :: "r"(dst), "l"(src), "r"(v ? 16 : 0) : "memory");
}
__device__ __forceinline__ void ldsm_x4(uint32_t addr, uint32_t* r) {
    asm volatile("ldmatrix.sync.aligned.m8n8.x4.shared.b16 {%0,%1,%2,%3}, [%4];"
        : "=r"(r[0]), "=r"(r[1]), "=r"(r[2]), "=r"(r[3]) : "r"(addr));
}
__device__ __forceinline__ void mma_bf16(float* c, const uint32_t* a, const uint32_t* b) {
    asm volatile("mma.sync.aligned.m16n8k16.row.col.f32.bf16.bf16.f32 "
        "{%0,%1,%2,%3}, {%4,%5,%6,%7}, {%8,%9}, {%0,%1,%2,%3};"
        : "+f"(c[0]), "+f"(c[1]), "+f"(c[2]), "+f"(c[3])
        : "r"(a[0]), "r"(a[1]), "r"(a[2]), "r"(a[3]), "r"(b[0]), "r"(b[1]));
}

// ---------------------------------------------------------------------------
// fp32 -> bf16 hi/lo split (A operand), vectorized by 4
// ---------------------------------------------------------------------------
__global__ __launch_bounds__(256) void split_a_kernel(
    const float* __restrict__ A, __nv_bfloat16* __restrict__ Ah,
    __nv_bfloat16* __restrict__ Al, int n4)
{
    int i = blockIdx.x * 256 + threadIdx.x;
    if (i >= n4) return;
    float4 a = ((const float4*)A)[i];
    __nv_bfloat16 h0 = __float2bfloat16_rn(a.x);
    __nv_bfloat16 h1 = __float2bfloat16_rn(a.y);
    __nv_bfloat16 h2 = __float2bfloat16_rn(a.z);
    __nv_bfloat16 h3 = __float2bfloat16_rn(a.w);
    __nv_bfloat16 l0 = __float2bfloat16_rn(a.x - __bfloat162float(h0));
    __nv_bfloat16 l1 = __float2bfloat16_rn(a.y - __bfloat162float(h1));
    __nv_bfloat16 l2 = __float2bfloat16_rn(a.z - __bfloat162float(h2));
    __nv_bfloat16 l3 = __float2bfloat16_rn(a.w - __bfloat162float(h3));
    ((__nv_bfloat162*)Ah)[2 * i + 0] = __nv_bfloat162(h0, h1);
    ((__nv_bfloat162*)Ah)[2 * i + 1] = __nv_bfloat162(h2, h3);
    ((__nv_bfloat162*)Al)[2 * i + 0] = __nv_bfloat162(l0, l1);
    ((__nv_bfloat162*)Al)[2 * i + 1] = __nv_bfloat162(l2, l3);
}

// All 4 weight matrices -> concat transposed split buffer in ONE launch.
__global__ __launch_bounds__(256) void split_w_kernel(
    const float* __restrict__ wv, const float* __restrict__ wo,
    const float* __restrict__ wa, const float* __restrict__ ww,
    __nv_bfloat16* __restrict__ Bh, __nv_bfloat16* __restrict__ Bl)
{
    int idx = blockIdx.x * 256 + threadIdx.x;   // 0 .. 896*256-1
    int nout = idx >> 8;
    int k = idx & 255;
    const float* src; int nloc, Nc;
    if (nout < 256)      { src = wv; nloc = nout;       Nc = 256; }
    else if (nout < 512) { src = wo; nloc = nout - 256; Nc = 256; }
    else if (nout < 640) { src = wa; nloc = nout - 512; Nc = 128; }
    else                 { src = ww; nloc = nout - 640; Nc = 256; }
    float b = src[k * Nc + nloc];
    __nv_bfloat16 h = __float2bfloat16_rn(b);
    __nv_bfloat16 l = __float2bfloat16_rn(b - __bfloat162float(h));
    Bh[idx] = h;
    Bl[idx] = l;
}

// ---------------------------------------------------------------------------
// Tensor-core GEMM via mma.sync bf16, 3-term split, cp.async double buffer.
// CTA tile 128x128, K=256 (8 chunks of 32). 8 warps = 4(M) x 2(N), warp 32x64.
// ---------------------------------------------------------------------------
#define PADK 40
#define SM_AH 0
#define SM_AL 10240
#define SM_BH 20480
#define SM_BL 30720
#define SMEM_BYTES (40960 * 2)

__global__ __launch_bounds__(256) void gemm_mma_kernel(
    const __nv_bfloat16* __restrict__ Ah, const __nv_bfloat16* __restrict__ Al,
    const __nv_bfloat16* __restrict__ Bth, const __nv_bfloat16* __restrict__ Btl,
    float* C0, float* C1, float* C2,
    const float* b0, const float* b1, const float* b2,
    int M, int fused)
{
    extern __shared__ __align__(16) char smem[];
    const uint32_t sbase = smem_u32(smem);

    const int tid  = threadIdx.x;
    const int lane = tid & 31;
    const int wid  = tid >> 5;
    const int wm   = wid & 3;
    const int wn   = wid >> 2;
    const int bm   = blockIdx.x * 128;
    const int bn   = blockIdx.y * 128;

    float* Cp; const float* bp; int stride, coloff;
    if (fused) {
        if (blockIdx.y < 2)      { Cp = C0; bp = b0; stride = 256; coloff = bn; }
        else if (blockIdx.y < 4) { Cp = C1; bp = b1; stride = 256; coloff = bn - 256; }
        else                     { Cp = C2; bp = b2; stride = 128; coloff = 0; }
    } else { Cp = C0; bp = b0; stride = 256; coloff = bn; }

    float acc[2][8][4];
#pragma unroll
    for (int i = 0; i < 2; i++)
#pragma unroll
        for (int j = 0; j < 8; j++)
#pragma unroll
            for (int t = 0; t < 4; t++) acc[i][j][t] = 0.f;

    auto load_chunk = [&](int kk, int buf) {
        const uint32_t ab = buf * 5120;
#pragma unroll
        for (int t = 0; t < 2; t++) {
            int idx = tid + 256 * t;
            int row = idx >> 2, seg = idx & 3;
            uint32_t d = (uint32_t)(row * PADK + seg * 8) * 2;
            bool va = (bm + row) < M;
            const __nv_bfloat16* sah = Ah + (size_t)(bm + row) * 256 + kk * 32 + seg * 8;
            const __nv_bfloat16* sal = Al + (size_t)(bm + row) * 256 + kk * 32 + seg * 8;
            cpa16(sbase + (SM_AH + ab) * 2 + d, sah, va);
            cpa16(sbase + (SM_AL + ab) * 2 + d, sal, va);
            const __nv_bfloat16* sbh = Bth + (size_t)(bn + row) * 256 + kk * 32 + seg * 8;
            const __nv_bfloat16* sbl = Btl + (size_t)(bn + row) * 256 + kk * 32 + seg * 8;
            cpa16(sbase + (SM_BH + ab) * 2 + d, sbh, true);
            cpa16(sbase + (SM_BL + ab) * 2 + d, sbl, true);
        }
        asm volatile("cp.async.commit_group;" ::: "memory");
    };

    load_chunk(0, 0);

    for (int kk = 0; kk < 8; kk++) {
        asm volatile("cp.async.wait_group 0;" ::: "memory");
        __syncthreads();
        if (kk < 7) load_chunk(kk + 1, (kk + 1) & 1);

        const uint32_t ab = (kk & 1) * 5120;
#pragma unroll
        for (int ks = 0; ks < 2; ks++) {
            uint32_t ah[2][4], alr[2][4];
#pragma unroll
            for (int mt = 0; mt < 2; mt++) {
                int row = wm * 32 + mt * 16 + (lane & 15);
                int col = ks * 16 + (lane >> 4) * 8;
                ldsm_x4(sbase + (uint32_t)(SM_AH + ab + row * PADK + col) * 2, ah[mt]);
                ldsm_x4(sbase + (uint32_t)(SM_AL + ab + row * PADK + col) * 2, alr[mt]);
            }
#pragma unroll
            for (int q = 0; q < 4; q++) {
                int rowB = wn * 64 + q * 16 + (lane & 7) + ((lane >> 4) & 1) * 8;
                int colB = ((lane >> 3) & 1) * 8 + ks * 16;
                uint32_t bh[4], bl[4];
                ldsm_x4(sbase + (uint32_t)(SM_BH + ab + rowB * PADK + colB) * 2, bh);
                ldsm_x4(sbase + (uint32_t)(SM_BL + ab + rowB * PADK + colB) * 2, bl);
#pragma unroll
                for (int mt = 0; mt < 2; mt++) {
                    mma_bf16(acc[mt][2 * q + 0], ah[mt], bh + 0);
                    mma_bf16(acc[mt][2 * q + 1], ah[mt], bh + 2);
                    mma_bf16(acc[mt][2 * q + 0], ah[mt], bl + 0);
                    mma_bf16(acc[mt][2 * q + 1], ah[mt], bl + 2);
                    mma_bf16(acc[mt][2 * q + 0], alr[mt], bh + 0);
                    mma_bf16(acc[mt][2 * q + 1], alr[mt], bh + 2);
                }
            }
        }
        __syncthreads();
    }

#pragma unroll
    for (int mt = 0; mt < 2; mt++) {
        int r0 = bm + wm * 32 + mt * 16 + (lane >> 2);
        int r1 = r0 + 8;
#pragma unroll
        for (int nt = 0; nt < 8; nt++) {
            int c = coloff + wn * 64 + nt * 8 + 2 * (lane & 3);
            float bb0 = bp[c], bb1 = bp[c + 1];
            if (r0 < M) {
                float2 v = make_float2(acc[mt][nt][0] + bb0, acc[mt][nt][1] + bb1);
                *(float2*)&Cp[(size_t)r0 * stride + c] = v;
            }
            if (r1 < M) {
                float2 v = make_float2(acc[mt][nt][2] + bb0, acc[mt][nt][3] + bb1);
                *(float2*)&Cp[(size_t)r1 * stride + c] = v;
            }
        }
    }
}

// ---------------------------------------------------------------------------
// Deformable sampling v2: block = 1 query.
// Prep (128 thr = head x point): softmax + bilinear weights/addresses -> smem.
// Gather (warp = head): lane = (corner = lane>>3, 4 channels = (lane&7)*4);
// one LDG.128 per point, weights via conflict-free LDS, xor-reduce corners.
// Emits bf16 hi/lo split directly (feeds GEMM2).
// ---------------------------------------------------------------------------
__global__ __launch_bounds__(256) void sample_kernel(
    const float* __restrict__ value,
    const float* __restrict__ off,
    const float* __restrict__ logits,
    const float* __restrict__ ref,
    __nv_bfloat16* __restrict__ outh,
    __nv_bfloat16* __restrict__ outl)
{
    const unsigned FULL = 0xffffffffu;
    __shared__ int   s_addr[HEADS * 16 * 4];
    __shared__ float s_w   [HEADS * 16 * 4];

    const int qg  = blockIdx.x;
    const int n   = qg / LQ;
    const int tid = threadIdx.x;

    if (tid < 128) {
        const int h = tid >> 4;
        const int p = tid & 15;
        const int l = p >> 2;

        float lg = logits[(size_t)qg * 128 + h * 16 + p];
        float mx = lg;
#pragma unroll
        for (int o = 8; o > 0; o >>= 1) mx = fmaxf(mx, __shfl_xor_sync(FULL, mx, o));
        float e = __expf(lg - mx);
        float sum = e;
#pragma unroll
        for (int o = 8; o > 0; o >>= 1) sum += __shfl_xor_sync(FULL, sum, o);
        const float aw = __fdividef(e, sum);

        const int W  = 96 >> l;
        const int S0 = 12288 - 3 * (4096 >> (2 * l));
        const float rx = ref[(size_t)qg * (LEVELS * 2) + l * 2 + 0] * (float)W;
        const float ry = ref[(size_t)qg * (LEVELS * 2) + l * 2 + 1] * (float)W;
        const float ox = off[(size_t)qg * DIM + h * 32 + p * 2 + 0];
        const float oy = off[(size_t)qg * DIM + h * 32 + p * 2 + 1];
        const float x = rx + ox - 0.5f;
        const float y = ry + oy - 0.5f;
        const float x0f = floorf(x), y0f = floorf(y);
        const int x0 = (int)x0f, y0 = (int)y0f;
        const float fx = x - x0f, fy = y - y0f;

        const float vx0 = (x0 >= 0 && x0 < W) ? 1.f : 0.f;
        const float vx1 = (x0 + 1 >= 0 && x0 + 1 < W) ? 1.f : 0.f;
        const float vy0 = (y0 >= 0 && y0 < W) ? 1.f : 0.f;
        const float vy1 = (y0 + 1 >= 0 && y0 + 1 < W) ? 1.f : 0.f;
        const float wx0 = (1.f - fx) * vx0;
        const float wx1 = fx * vx1;
        const float wy0 = (1.f - fy) * aw * vy0;
        const float wy1 = fy * aw * vy1;
        const int c0 = min(max(x0, 0), W - 1) * DIM;
        const int c1 = min(max(x0 + 1, 0), W - 1) * DIM;
        const int r0 = (S0 + min(max(y0, 0), W - 1) * W) * DIM;
        const int r1 = (S0 + min(max(y0 + 1, 0), W - 1) * W) * DIM;

        const int b = tid * 4;
        s_addr[b + 0] = r0 + c0;  s_w[b + 0] = wx0 * wy0;
        s_addr[b + 1] = r0 + c1;  s_w[b + 1] = wx1 * wy0;
        s_addr[b + 2] = r1 + c0;  s_w[b + 2] = wx0 * wy1;
        s_addr[b + 3] = r1 + c1;  s_w[b + 3] = wx1 * wy1;
    }
    __syncthreads();

    const int h    = tid >> 5;
    const int lane = tid & 31;
    const int c    = lane >> 3;        // corner 0..3
    const int ch   = (lane & 7) * 4;   // channel base 0..28

    const float* vb = value + (size_t)n * (LQ * DIM) + h * 32 + ch;
    float4 acc = make_float4(0.f, 0.f, 0.f, 0.f);
#pragma unroll
    for (int p = 0; p < 16; p++) {
        const int si = (h * 16 + p) * 4 + c;
        const int a  = s_addr[si];
        const float w = s_w[si];
        const float4 v = *(const float4*)(vb + a);
        acc.x = fmaf(w, v.x, acc.x);
        acc.y = fmaf(w, v.y, acc.y);
        acc.z = fmaf(w, v.z, acc.z);
        acc.w = fmaf(w, v.w, acc.w);
    }
    // reduce the 4 corner groups (xor 8, then 16)
#pragma unroll
    for (int o = 8; o <= 16; o <<= 1) {
        acc.x += __shfl_xor_sync(FULL, acc.x, o);
        acc.y += __shfl_xor_sync(FULL, acc.y, o);
        acc.z += __shfl_xor_sync(FULL, acc.z, o);
        acc.w += __shfl_xor_sync(FULL, acc.w, o);
    }
    if (lane < 8) {
        const size_t o0 = (size_t)qg * DIM + h * 32 + ch;
        float vv[4] = {acc.x, acc.y, acc.z, acc.w};
        __nv_bfloat16 hh[4], ll[4];
#pragma unroll
        for (int j = 0; j < 4; j++) {
            hh[j] = __float2bfloat16_rn(vv[j]);
            ll[j] = __float2bfloat16_rn(vv[j] - __bfloat162float(hh[j]));
        }
        uint2 ph, pl;
        ph.x = ((uint32_t)*(uint16_t*)&hh[1] << 16) | *(uint16_t*)&hh[0];
        ph.y = ((uint32_t)*(uint16_t*)&hh[3] << 16) | *(uint16_t*)&hh[2];
        pl.x = ((uint32_t)*(uint16_t*)&ll[1] << 16) | *(uint16_t*)&ll[0];
        pl.y = ((uint32_t)*(uint16_t*)&ll[3] << 16) | *(uint16_t*)&ll[2];
        *(uint2*)(outh + o0) = ph;
        *(uint2*)(outl + o0) = pl;
    }
}

// ---------------------------------------------------------------------------
// Residual + LayerNorm
// ---------------------------------------------------------------------------
__global__ __launch_bounds__(256) void ln_kernel(
    const float* __restrict__ src, const float* __restrict__ y,
    const float* __restrict__ gamma, const float* __restrict__ beta,
    float* __restrict__ out)
{
    const int row = blockIdx.x;
    const int t = threadIdx.x;
    const size_t idx = (size_t)row * DIM + t;
    const float x = src[idx] + y[idx];

    float s = x, s2 = x * x;
#pragma unroll
    for (int o = 16; o > 0; o >>= 1) {
        s  += __shfl_down_sync(0xffffffffu, s, o);
        s2 += __shfl_down_sync(0xffffffffu, s2, o);
    }
    __shared__ float ss[8], ss2[8];
    const int w = t >> 5;
    if ((t & 31) == 0) { ss[w] = s; ss2[w] = s2; }
    __syncthreads();
    float sum = 0.f, sum2 = 0.f;
#pragma unroll
    for (int i = 0; i < 8; i++) { sum += ss[i]; sum2 += ss2[i]; }

    const float mu  = sum * (1.0f / DIM);
    const float var = sum2 * (1.0f / DIM) - mu * mu;
    const float r = rsqrtf(var + 1e-5f);
    out[idx] = (x - mu) * r * gamma[t] + beta[t];
}

// ---------------------------------------------------------------------------
extern "C" void kernel_launch(void* const* d_in, const int* in_sizes, int n_in,
                              void* d_out, int out_size)
{
    const float* src    = (const float*)d_in[0];
    const float* refpts = (const float*)d_in[1];
    const float* w_value = (const float*)d_in[4];
    const float* b_value = (const float*)d_in[5];
    const float* w_off   = (const float*)d_in[6];
    const float* b_off   = (const float*)d_in[7];
    const float* w_attn  = (const float*)d_in[8];
    const float* b_attn  = (const float*)d_in[9];
    const float* w_out   = (const float*)d_in[10];
    const float* b_out   = (const float*)d_in[11];
    const float* gamma   = (const float*)d_in[12];
    const float* beta    = (const float*)d_in[13];
    float* out = (float*)d_out;

    float *gv, *go, *ga, *g2;
    cudaGetSymbolAddress((void**)&gv,  g_value);
    cudaGetSymbolAddress((void**)&go,  g_off);
    cudaGetSymbolAddress((void**)&ga,  g_attn);
    cudaGetSymbolAddress((void**)&g2,  g_out2);
    __nv_bfloat16 *ah, *al, *bch, *bcl;
    cudaGetSymbolAddress((void**)&ah,  g_ah);
    cudaGetSymbolAddress((void**)&al,  g_al);
    cudaGetSymbolAddress((void**)&bch, g_btc_h);
    cudaGetSymbolAddress((void**)&bcl, g_btc_l);

    const int M = MROWS;
    cudaFuncSetAttribute(gemm_mma_kernel, cudaFuncAttributeMaxDynamicSharedMemorySize, SMEM_BYTES);

    dim3 blk(256);
    const int n4 = M * DIM / 4;
    const int gtiles = (M + 127) / 128;   // 192

    // all weight splits in one launch
    split_w_kernel<<<896, blk>>>(w_value, w_off, w_attn, w_out, bch, bcl);

    // src split
    split_a_kernel<<<(n4 + 255) / 256, blk>>>(src, ah, al, n4);

    // fused input projections: N=640 (value 256 | off 256 | attn 128)
    gemm_mma_kernel<<<dim3(gtiles, 5), blk, SMEM_BYTES>>>(
        ah, al, bch, bcl, gv, go, ga, b_value, b_off, b_attn, M, 1);

    // deformable sampling (emits bf16 split directly into ah/al)
    sample_kernel<<<MROWS, blk>>>(gv, go, ga, refpts, ah, al);

    // output projection
    gemm_mma_kernel<<<dim3(gtiles, 2), blk, SMEM_BYTES>>>(
        ah, al, bch + 640 * 256, bcl + 640 * 256, g2, nullptr, nullptr,
        b_out, nullptr, nullptr, M, 0);

    // residual + layernorm
    ln_kernel<<<MROWS, blk>>>(src, g2, gamma, beta, out);
}

// round 7
// speedup vs baseline: 2.4400x; 1.0685x over previous
#include <cuda_runtime.h>
#include <cuda_bf16.h>
#include <cuda_fp16.h>
#include <cstdint>
#include <math.h>

#define NB      2
#define LQ      12240
#define DIM     256
#define HEADS   8
#define LEVELS  4
#define POINTS  4
#define HD      32
#define MROWS   (NB * LQ)   // 24480

// ------------------------- scratch (no allocs allowed) ----------------------
__device__ __half g_value_h[MROWS * DIM];
__device__ float g_off    [MROWS * DIM];
__device__ float g_attn   [MROWS * HEADS * 16];
__device__ float g_out2   [MROWS * DIM];

// bf16 split operands
__device__ __nv_bfloat16 g_ah[MROWS * DIM];
__device__ __nv_bfloat16 g_al[MROWS * DIM];
// concatenated transposed+split weights [n][k] K-major:
// rows 0-255 value, 256-511 off, 512-639 attn, 640-895 out
__device__ __nv_bfloat16 g_btc_h[896 * 256];
__device__ __nv_bfloat16 g_btc_l[896 * 256];

// ------------------------------ PTX helpers ---------------------------------
__device__ __forceinline__ uint32_t smem_u32(const void* p) {
    uint32_t a;
    asm("{ .reg .u64 t; cvta.to.shared.u64 t, %1; cvt.u32.u64 %0, t; }" : "=r"(a) : "l"(p));
    return a;
}
__device__ __forceinline__ void cpa16(uint32_t dst, const void* src, bool v) {
    asm volatile("cp.async.cg.shared.global [%0], [%1], 16, %2;"
        :: "r"(dst), "l"(src), "r"(v ? 16 : 0) : "memory");
}
__device__ __forceinline__ void ldsm_x4(uint32_t addr, uint32_t* r) {
    asm volatile("ldmatrix.sync.aligned.m8n8.x4.shared.b16 {%0,%1,%2,%3}, [%4];"
        : "=r"(r[0]), "=r"(r[1]), "=r"(r[2]), "=r"(r[3]) : "r"(addr));
}
__device__ __forceinline__ void mma_bf16(float* c, const uint32_t* a, const uint32_t* b) {
    asm volatile("mma.sync.aligned.m16n8k16.row.col.f32.bf16.bf16.f32 "
        "{%0,%1,%2,%3}, {%4,%5,%6,%7}, {%8,%9}, {%0,%1,%2,%3};"
        : "+f"(c[0]), "+f"(c[1]), "+f"(c[2]), "+f"(c[3])
        : "r"(a[0]), "r"(a[1]), "r"(a[2]), "r"(a[3]), "r"(b[0]), "r"(b[1]));
}

// ---------------------------------------------------------------------------
// Fused split kernel: blocks [0,896) -> weight transpose+split,
// blocks [896, ...) -> A (src) hi/lo split.
// ---------------------------------------------------------------------------
__global__ __launch_bounds__(256) void split_all_kernel(
    const float* __restrict__ A, __nv_bfloat16* __restrict__ Ah,
    __nv_bfloat16* __restrict__ Al, int n4,
    const float* __restrict__ wv, const float* __restrict__ wo,
    const float* __restrict__ wa, const float* __restrict__ ww,
    __nv_bfloat16* __restrict__ Bh, __nv_bfloat16* __restrict__ Bl)
{
    const int bid = blockIdx.x;
    if (bid < 896) {
        int idx = bid * 256 + threadIdx.x;
        int nout = idx >> 8;
        int k = idx & 255;
        const float* src; int nloc, Nc;
        if (nout < 256)      { src = wv; nloc = nout;       Nc = 256; }
        else if (nout < 512) { src = wo; nloc = nout - 256; Nc = 256; }
        else if (nout < 640) { src = wa; nloc = nout - 512; Nc = 128; }
        else                 { src = ww; nloc = nout - 640; Nc = 256; }
        float b = src[k * Nc + nloc];
        __nv_bfloat16 h = __float2bfloat16_rn(b);
        __nv_bfloat16 l = __float2bfloat16_rn(b - __bfloat162float(h));
        Bh[idx] = h;
        Bl[idx] = l;
    } else {
        int i = (bid - 896) * 256 + threadIdx.x;
        if (i >= n4) return;
        float4 a = ((const float4*)A)[i];
        __nv_bfloat16 h0 = __float2bfloat16_rn(a.x);
        __nv_bfloat16 h1 = __float2bfloat16_rn(a.y);
        __nv_bfloat16 h2 = __float2bfloat16_rn(a.z);
        __nv_bfloat16 h3 = __float2bfloat16_rn(a.w);
        __nv_bfloat16 l0 = __float2bfloat16_rn(a.x - __bfloat162float(h0));
        __nv_bfloat16 l1 = __float2bfloat16_rn(a.y - __bfloat162float(h1));
        __nv_bfloat16 l2 = __float2bfloat16_rn(a.z - __bfloat162float(h2));
        __nv_bfloat16 l3 = __float2bfloat16_rn(a.w - __bfloat162float(h3));
        ((__nv_bfloat162*)Ah)[2 * i + 0] = __nv_bfloat162(h0, h1);
        ((__nv_bfloat162*)Ah)[2 * i + 1] = __nv_bfloat162(h2, h3);
        ((__nv_bfloat162*)Al)[2 * i + 0] = __nv_bfloat162(l0, l1);
        ((__nv_bfloat162*)Al)[2 * i + 1] = __nv_bfloat162(l2, l3);
    }
}

// ---------------------------------------------------------------------------
// Tensor-core GEMM via mma.sync bf16, 3-term split, cp.async double buffer.
// CTA tile 128x128, K=256 (8 chunks of 32). 8 warps = 4(M) x 2(N), warp 32x64.
// fused=1: blockIdx.y 0-1 -> value, written fp16 to C0h; 2-3 -> C1; 4 -> C2
// ---------------------------------------------------------------------------
#define PADK 40
#define SM_AH 0
#define SM_AL 10240
#define SM_BH 20480
#define SM_BL 30720
#define SMEM_BYTES (40960 * 2)

__global__ __launch_bounds__(256) void gemm_mma_kernel(
    const __nv_bfloat16* __restrict__ Ah, const __nv_bfloat16* __restrict__ Al,
    const __nv_bfloat16* __restrict__ Bth, const __nv_bfloat16* __restrict__ Btl,
    float* C0, __half* C0h, float* C1, float* C2,
    const float* b0, const float* b1, const float* b2,
    int M, int fused)
{
    extern __shared__ __align__(16) char smem[];
    const uint32_t sbase = smem_u32(smem);

    const int tid  = threadIdx.x;
    const int lane = tid & 31;
    const int wid  = tid >> 5;
    const int wm   = wid & 3;
    const int wn   = wid >> 2;
    const int bm   = blockIdx.x * 128;
    const int bn   = blockIdx.y * 128;

    float* Cp; const float* bp; int stride, coloff; bool halfOut = false;
    if (fused) {
        if (blockIdx.y < 2)      { Cp = C0; bp = b0; stride = 256; coloff = bn; halfOut = true; }
        else if (blockIdx.y < 4) { Cp = C1; bp = b1; stride = 256; coloff = bn - 256; }
        else                     { Cp = C2; bp = b2; stride = 128; coloff = 0; }
    } else { Cp = C0; bp = b0; stride = 256; coloff = bn; }

    float acc[2][8][4];
#pragma unroll
    for (int i = 0; i < 2; i++)
#pragma unroll
        for (int j = 0; j < 8; j++)
#pragma unroll
            for (int t = 0; t < 4; t++) acc[i][j][t] = 0.f;

    auto load_chunk = [&](int kk, int buf) {
        const uint32_t ab = buf * 5120;
#pragma unroll
        for (int t = 0; t < 2; t++) {
            int idx = tid + 256 * t;
            int row = idx >> 2, seg = idx & 3;
            uint32_t d = (uint32_t)(row * PADK + seg * 8) * 2;
            bool va = (bm + row) < M;
            const __nv_bfloat16* sah = Ah + (size_t)(bm + row) * 256 + kk * 32 + seg * 8;
            const __nv_bfloat16* sal = Al + (size_t)(bm + row) * 256 + kk * 32 + seg * 8;
            cpa16(sbase + (SM_AH + ab) * 2 + d, sah, va);
            cpa16(sbase + (SM_AL + ab) * 2 + d, sal, va);
            const __nv_bfloat16* sbh = Bth + (size_t)(bn + row) * 256 + kk * 32 + seg * 8;
            const __nv_bfloat16* sbl = Btl + (size_t)(bn + row) * 256 + kk * 32 + seg * 8;
            cpa16(sbase + (SM_BH + ab) * 2 + d, sbh, true);
            cpa16(sbase + (SM_BL + ab) * 2 + d, sbl, true);
        }
        asm volatile("cp.async.commit_group;" ::: "memory");
    };

    load_chunk(0, 0);

    for (int kk = 0; kk < 8; kk++) {
        asm volatile("cp.async.wait_group 0;" ::: "memory");
        __syncthreads();
        if (kk < 7) load_chunk(kk + 1, (kk + 1) & 1);

        const uint32_t ab = (kk & 1) * 5120;
#pragma unroll
        for (int ks = 0; ks < 2; ks++) {
            uint32_t ah[2][4], alr[2][4];
#pragma unroll
            for (int mt = 0; mt < 2; mt++) {
                int row = wm * 32 + mt * 16 + (lane & 15);
                int col = ks * 16 + (lane >> 4) * 8;
                ldsm_x4(sbase + (uint32_t)(SM_AH + ab + row * PADK + col) * 2, ah[mt]);
                ldsm_x4(sbase + (uint32_t)(SM_AL + ab + row * PADK + col) * 2, alr[mt]);
            }
#pragma unroll
            for (int q = 0; q < 4; q++) {
                int rowB = wn * 64 + q * 16 + (lane & 7) + ((lane >> 4) & 1) * 8;
                int colB = ((lane >> 3) & 1) * 8 + ks * 16;
                uint32_t bh[4], bl[4];
                ldsm_x4(sbase + (uint32_t)(SM_BH + ab + rowB * PADK + colB) * 2, bh);
                ldsm_x4(sbase + (uint32_t)(SM_BL + ab + rowB * PADK + colB) * 2, bl);
#pragma unroll
                for (int mt = 0; mt < 2; mt++) {
                    mma_bf16(acc[mt][2 * q + 0], ah[mt], bh + 0);
                    mma_bf16(acc[mt][2 * q + 1], ah[mt], bh + 2);
                    mma_bf16(acc[mt][2 * q + 0], ah[mt], bl + 0);
                    mma_bf16(acc[mt][2 * q + 1], ah[mt], bl + 2);
                    mma_bf16(acc[mt][2 * q + 0], alr[mt], bh + 0);
                    mma_bf16(acc[mt][2 * q + 1], alr[mt], bh + 2);
                }
            }
        }
        __syncthreads();
    }

#pragma unroll
    for (int mt = 0; mt < 2; mt++) {
        int r0 = bm + wm * 32 + mt * 16 + (lane >> 2);
        int r1 = r0 + 8;
#pragma unroll
        for (int nt = 0; nt < 8; nt++) {
            int c = coloff + wn * 64 + nt * 8 + 2 * (lane & 3);
            float bb0 = bp[c], bb1 = bp[c + 1];
            if (halfOut) {
                if (r0 < M)
                    *(__half2*)&C0h[(size_t)r0 * 256 + c] =
                        __floats2half2_rn(acc[mt][nt][0] + bb0, acc[mt][nt][1] + bb1);
                if (r1 < M)
                    *(__half2*)&C0h[(size_t)r1 * 256 + c] =
                        __floats2half2_rn(acc[mt][nt][2] + bb0, acc[mt][nt][3] + bb1);
            } else {
                if (r0 < M) {
                    float2 v = make_float2(acc[mt][nt][0] + bb0, acc[mt][nt][1] + bb1);
                    *(float2*)&Cp[(size_t)r0 * stride + c] = v;
                }
                if (r1 < M) {
                    float2 v = make_float2(acc[mt][nt][2] + bb0, acc[mt][nt][3] + bb1);
                    *(float2*)&Cp[(size_t)r1 * stride + c] = v;
                }
            }
        }
    }
}

// ---------------------------------------------------------------------------
// Deformable sampling v3: block = 1 query, value in fp16.
// Prep (128 thr = head x point): softmax + bilinear -> packed (addr, w) smem.
// Gather (warp = head): lane = (corner = lane>>3, 4 channels = (lane&7)*4);
// one LDG.64 (4 fp16) per point-corner-group, packed LDS.64 for (addr, w).
// Emits bf16 hi/lo split directly (feeds GEMM2).
// ---------------------------------------------------------------------------
__global__ __launch_bounds__(256) void sample_kernel(
    const __half* __restrict__ value,
    const float* __restrict__ off,
    const float* __restrict__ logits,
    const float* __restrict__ ref,
    __nv_bfloat16* __restrict__ outh,
    __nv_bfloat16* __restrict__ outl)
{
    const unsigned FULL = 0xffffffffu;
    __shared__ float2 s_aw[HEADS * 16 * 4];   // (addr_as_float, weight)

    const int qg  = blockIdx.x;
    const int n   = qg / LQ;
    const int tid = threadIdx.x;

    if (tid < 128) {
        const int h = tid >> 4;
        const int p = tid & 15;
        const int l = p >> 2;

        float lg = logits[(size_t)qg * 128 + h * 16 + p];
        float mx = lg;
#pragma unroll
        for (int o = 8; o > 0; o >>= 1) mx = fmaxf(mx, __shfl_xor_sync(FULL, mx, o));
        float e = __expf(lg - mx);
        float sum = e;
#pragma unroll
        for (int o = 8; o > 0; o >>= 1) sum += __shfl_xor_sync(FULL, sum, o);
        const float aw = __fdividef(e, sum);

        const int W  = 96 >> l;
        const int S0 = 12288 - 3 * (4096 >> (2 * l));
        const float rx = ref[(size_t)qg * (LEVELS * 2) + l * 2 + 0] * (float)W;
        const float ry = ref[(size_t)qg * (LEVELS * 2) + l * 2 + 1] * (float)W;
        const float ox = off[(size_t)qg * DIM + h * 32 + p * 2 + 0];
        const float oy = off[(size_t)qg * DIM + h * 32 + p * 2 + 1];
        const float x = rx + ox - 0.5f;
        const float y = ry + oy - 0.5f;
        const float x0f = floorf(x), y0f = floorf(y);
        const int x0 = (int)x0f, y0 = (int)y0f;
        const float fx = x - x0f, fy = y - y0f;

        const float vx0 = (x0 >= 0 && x0 < W) ? 1.f : 0.f;
        const float vx1 = (x0 + 1 >= 0 && x0 + 1 < W) ? 1.f : 0.f;
        const float vy0 = (y0 >= 0 && y0 < W) ? 1.f : 0.f;
        const float vy1 = (y0 + 1 >= 0 && y0 + 1 < W) ? 1.f : 0.f;
        const float wx0 = (1.f - fx) * vx0;
        const float wx1 = fx * vx1;
        const float wy0 = (1.f - fy) * aw * vy0;
        const float wy1 = fy * aw * vy1;
        const int c0 = min(max(x0, 0), W - 1) * DIM;
        const int c1 = min(max(x0 + 1, 0), W - 1) * DIM;
        const int r0 = (S0 + min(max(y0, 0), W - 1) * W) * DIM;
        const int r1 = (S0 + min(max(y0 + 1, 0), W - 1) * W) * DIM;

        const int b = tid * 4;
        s_aw[b + 0] = make_float2(__int_as_float(r0 + c0), wx0 * wy0);
        s_aw[b + 1] = make_float2(__int_as_float(r0 + c1), wx1 * wy0);
        s_aw[b + 2] = make_float2(__int_as_float(r1 + c0), wx0 * wy1);
        s_aw[b + 3] = make_float2(__int_as_float(r1 + c1), wx1 * wy1);
    }
    __syncthreads();

    const int h    = tid >> 5;
    const int lane = tid & 31;
    const int c    = lane >> 3;        // corner 0..3
    const int ch   = (lane & 7) * 4;   // channel base 0..28

    const __half* vb = value + (size_t)n * (LQ * DIM) + h * 32 + ch;
    float4 acc = make_float4(0.f, 0.f, 0.f, 0.f);
#pragma unroll
    for (int p = 0; p < 16; p++) {
        const float2 t = s_aw[(h * 16 + p) * 4 + c];
        const int a = __float_as_int(t.x);
        const float w = t.y;
        const uint2 raw = *(const uint2*)(vb + a);
        const float2 v0 = __half22float2(*(const __half2*)&raw.x);
        const float2 v1 = __half22float2(*(const __half2*)&raw.y);
        acc.x = fmaf(w, v0.x, acc.x);
        acc.y = fmaf(w, v0.y, acc.y);
        acc.z = fmaf(w, v1.x, acc.z);
        acc.w = fmaf(w, v1.y, acc.w);
    }
#pragma unroll
    for (int o = 8; o <= 16; o <<= 1) {
        acc.x += __shfl_xor_sync(FULL, acc.x, o);
        acc.y += __shfl_xor_sync(FULL, acc.y, o);
        acc.z += __shfl_xor_sync(FULL, acc.z, o);
        acc.w += __shfl_xor_sync(FULL, acc.w, o);
    }
    if (lane < 8) {
        const size_t o0 = (size_t)qg * DIM + h * 32 + ch;
        float vv[4] = {acc.x, acc.y, acc.z, acc.w};
        __nv_bfloat16 hh[4], ll[4];
#pragma unroll
        for (int j = 0; j < 4; j++) {
            hh[j] = __float2bfloat16_rn(vv[j]);
            ll[j] = __float2bfloat16_rn(vv[j] - __bfloat162float(hh[j]));
        }
        uint2 ph, pl;
        ph.x = ((uint32_t)*(uint16_t*)&hh[1] << 16) | *(uint16_t*)&hh[0];
        ph.y = ((uint32_t)*(uint16_t*)&hh[3] << 16) | *(uint16_t*)&hh[2];
        pl.x = ((uint32_t)*(uint16_t*)&ll[1] << 16) | *(uint16_t*)&ll[0];
        pl.y = ((uint32_t)*(uint16_t*)&ll[3] << 16) | *(uint16_t*)&ll[2];
        *(uint2*)(outh + o0) = ph;
        *(uint2*)(outl + o0) = pl;
    }
}

// ---------------------------------------------------------------------------
// Residual + LayerNorm
// ---------------------------------------------------------------------------
__global__ __launch_bounds__(256) void ln_kernel(
    const float* __restrict__ src, const float* __restrict__ y,
    const float* __restrict__ gamma, const float* __restrict__ beta,
    float* __restrict__ out)
{
    const int row = blockIdx.x;
    const int t = threadIdx.x;
    const size_t idx = (size_t)row * DIM + t;
    const float x = src[idx] + y[idx];

    float s = x, s2 = x * x;
#pragma unroll
    for (int o = 16; o > 0; o >>= 1) {
        s  += __shfl_down_sync(0xffffffffu, s, o);
        s2 += __shfl_down_sync(0xffffffffu, s2, o);
    }
    __shared__ float ss[8], ss2[8];
    const int w = t >> 5;
    if ((t & 31) == 0) { ss[w] = s; ss2[w] = s2; }
    __syncthreads();
    float sum = 0.f, sum2 = 0.f;
#pragma unroll
    for (int i = 0; i < 8; i++) { sum += ss[i]; sum2 += ss2[i]; }

    const float mu  = sum * (1.0f / DIM);
    const float var = sum2 * (1.0f / DIM) - mu * mu;
    const float r = rsqrtf(var + 1e-5f);
    out[idx] = (x - mu) * r * gamma[t] + beta[t];
}

// ---------------------------------------------------------------------------
extern "C" void kernel_launch(void* const* d_in, const int* in_sizes, int n_in,
                              void* d_out, int out_size)
{
    const float* src    = (const float*)d_in[0];
    const float* refpts = (const float*)d_in[1];
    const float* w_value = (const float*)d_in[4];
    const float* b_value = (const float*)d_in[5];
    const float* w_off   = (const float*)d_in[6];
    const float* b_off   = (const float*)d_in[7];
    const float* w_attn  = (const float*)d_in[8];
    const float* b_attn  = (const float*)d_in[9];
    const float* w_out   = (const float*)d_in[10];
    const float* b_out   = (const float*)d_in[11];
    const float* gamma   = (const float*)d_in[12];
    const float* beta    = (const float*)d_in[13];
    float* out = (float*)d_out;

    float *go, *ga, *g2;
    __half* gvh;
    cudaGetSymbolAddress((void**)&gvh, g_value_h);
    cudaGetSymbolAddress((void**)&go,  g_off);
    cudaGetSymbolAddress((void**)&ga,  g_attn);
    cudaGetSymbolAddress((void**)&g2,  g_out2);
    __nv_bfloat16 *ah, *al, *bch, *bcl;
    cudaGetSymbolAddress((void**)&ah,  g_ah);
    cudaGetSymbolAddress((void**)&al,  g_al);
    cudaGetSymbolAddress((void**)&bch, g_btc_h);
    cudaGetSymbolAddress((void**)&bcl, g_btc_l);

    const int M = MROWS;
    cudaFuncSetAttribute(gemm_mma_kernel, cudaFuncAttributeMaxDynamicSharedMemorySize, SMEM_BYTES);

    dim3 blk(256);
    const int n4 = M * DIM / 4;
    const int gtiles = (M + 127) / 128;   // 192

    // fused weight + src splits
    split_all_kernel<<<896 + (n4 + 255) / 256, blk>>>(
        src, ah, al, n4, w_value, w_off, w_attn, w_out, bch, bcl);

    // fused input projections: N=640 (value 256 fp16 | off 256 | attn 128)
    gemm_mma_kernel<<<dim3(gtiles, 5), blk, SMEM_BYTES>>>(
        ah, al, bch, bcl, nullptr, gvh, go, ga, b_value, b_off, b_attn, M, 1);

    // deformable sampling (fp16 value; emits bf16 split into ah/al)
    sample_kernel<<<MROWS, blk>>>(gvh, go, ga, refpts, ah, al);

    // output projection
    gemm_mma_kernel<<<dim3(gtiles, 2), blk, SMEM_BYTES>>>(
        ah, al, bch + 640 * 256, bcl + 640 * 256, g2, nullptr, nullptr, nullptr,
        b_out, nullptr, nullptr, M, 0);

    // residual + layernorm
    ln_kernel<<<MROWS, blk>>>(src, g2, gamma, beta, out);
}

// round 8
// speedup vs baseline: 3.3110x; 1.3570x over previous
#include <cuda_runtime.h>
#include <cuda_fp16.h>
#include <cstdint>
#include <math.h>

#define NB      2
#define LQ      12240
#define DIM     256
#define HEADS   8
#define LEVELS  4
#define POINTS  4
#define HD      32
#define MROWS   (NB * LQ)   // 24480

// ------------------------- scratch (no allocs allowed) ----------------------
__device__ __half g_value_h[MROWS * DIM];
__device__ float  g_off    [MROWS * DIM];
__device__ float  g_attn   [MROWS * HEADS * 16];
__device__ float  g_out2   [MROWS * DIM];

// fp16 A operand (src, then attention output) and concatenated transposed
// weights [n][k] K-major: rows 0-255 value, 256-511 off, 512-639 attn, 640-895 out
__device__ __half g_af [MROWS * DIM];
__device__ __half g_btc[896 * 256];

// ------------------------------ PTX helpers ---------------------------------
__device__ __forceinline__ uint32_t smem_u32(const void* p) {
    uint32_t a;
    asm("{ .reg .u64 t; cvta.to.shared.u64 t, %1; cvt.u32.u64 %0, t; }" : "=r"(a) : "l"(p));
    return a;
}
__device__ __forceinline__ void cpa16(uint32_t dst, const void* src, bool v) {
    asm volatile("cp.async.cg.shared.global [%0], [%1], 16, %2;"
        :: "r"(dst), "l"(src), "r"(v ? 16 : 0) : "memory");
}
__device__ __forceinline__ void ldsm_x4(uint32_t addr, uint32_t* r) {
    asm volatile("ldmatrix.sync.aligned.m8n8.x4.shared.b16 {%0,%1,%2,%3}, [%4];"
        : "=r"(r[0]), "=r"(r[1]), "=r"(r[2]), "=r"(r[3]) : "r"(addr));
}
__device__ __forceinline__ void mma_f16(float* c, const uint32_t* a, const uint32_t* b) {
    asm volatile("mma.sync.aligned.m16n8k16.row.col.f32.f16.f16.f32 "
        "{%0,%1,%2,%3}, {%4,%5,%6,%7}, {%8,%9}, {%0,%1,%2,%3};"
        : "+f"(c[0]), "+f"(c[1]), "+f"(c[2]), "+f"(c[3])
        : "r"(a[0]), "r"(a[1]), "r"(a[2]), "r"(a[3]), "r"(b[0]), "r"(b[1]));
}

// ---------------------------------------------------------------------------
// Fused split kernel: blocks [0,896) -> weight transpose to fp16,
// blocks [896,...) -> src to fp16.
// ---------------------------------------------------------------------------
__global__ __launch_bounds__(256) void split_all_kernel(
    const float* __restrict__ A, __half* __restrict__ Af, int n4,
    const float* __restrict__ wv, const float* __restrict__ wo,
    const float* __restrict__ wa, const float* __restrict__ ww,
    __half* __restrict__ Bt)
{
    const int bid = blockIdx.x;
    if (bid < 896) {
        int idx = bid * 256 + threadIdx.x;
        int nout = idx >> 8;
        int k = idx & 255;
        const float* src; int nloc, Nc;
        if (nout < 256)      { src = wv; nloc = nout;       Nc = 256; }
        else if (nout < 512) { src = wo; nloc = nout - 256; Nc = 256; }
        else if (nout < 640) { src = wa; nloc = nout - 512; Nc = 128; }
        else                 { src = ww; nloc = nout - 640; Nc = 256; }
        Bt[idx] = __float2half_rn(src[k * Nc + nloc]);
    } else {
        int i = (bid - 896) * 256 + threadIdx.x;
        if (i >= n4) return;
        float4 a = ((const float4*)A)[i];
        __half2 p0 = __floats2half2_rn(a.x, a.y);
        __half2 p1 = __floats2half2_rn(a.z, a.w);
        uint2 v;
        v.x = *(uint32_t*)&p0;
        v.y = *(uint32_t*)&p1;
        *(uint2*)(Af + 4 * (size_t)i) = v;
    }
}

// ---------------------------------------------------------------------------
// fp16 tensor-core GEMM via mma.sync, 3-stage cp.async pipeline.
// CTA tile 128x128, K=256 (8 chunks of 32). 8 warps = 4(M) x 2(N), warp 32x64.
// fused=1: blockIdx.y 0-1 -> value (fp16 out), 2-3 -> off, 4 -> attn
// ---------------------------------------------------------------------------
#define PADK 40
#define STAGE_BYTES 20480     // A 10240 + B 10240
#define SMEM_BYTES (3 * STAGE_BYTES)

__global__ __launch_bounds__(256) void gemm_mma_kernel(
    const __half* __restrict__ Af, const __half* __restrict__ Bt,
    float* C0, __half* C0h, float* C1, float* C2,
    const float* b0, const float* b1, const float* b2,
    int M, int fused)
{
    extern __shared__ __align__(16) char smem[];
    const uint32_t sbase = smem_u32(smem);

    const int tid  = threadIdx.x;
    const int lane = tid & 31;
    const int wid  = tid >> 5;
    const int wm   = wid & 3;
    const int wn   = wid >> 2;
    const int bm   = blockIdx.x * 128;
    const int bn   = blockIdx.y * 128;

    float* Cp; const float* bp; int stride, coloff; bool halfOut = false;
    if (fused) {
        if (blockIdx.y < 2)      { Cp = C0; bp = b0; stride = 256; coloff = bn; halfOut = true; }
        else if (blockIdx.y < 4) { Cp = C1; bp = b1; stride = 256; coloff = bn - 256; }
        else                     { Cp = C2; bp = b2; stride = 128; coloff = 0; }
    } else { Cp = C0; bp = b0; stride = 256; coloff = bn; }

    float acc[2][8][4];
#pragma unroll
    for (int i = 0; i < 2; i++)
#pragma unroll
        for (int j = 0; j < 8; j++)
#pragma unroll
            for (int t = 0; t < 4; t++) acc[i][j][t] = 0.f;

    auto load_chunk = [&](int kk, int st) {
        const uint32_t base = sbase + st * STAGE_BYTES;
#pragma unroll
        for (int t = 0; t < 2; t++) {
            int idx = tid + 256 * t;
            int row = idx >> 2, seg = idx & 3;
            uint32_t d = (uint32_t)(row * PADK + seg * 8) * 2;
            bool va = (bm + row) < M;
            cpa16(base + d, Af + (size_t)(bm + row) * 256 + kk * 32 + seg * 8, va);
            cpa16(base + 10240 + d, Bt + (size_t)(bn + row) * 256 + kk * 32 + seg * 8, true);
        }
        asm volatile("cp.async.commit_group;" ::: "memory");
    };

    load_chunk(0, 0);
    load_chunk(1, 1);

    for (int kk = 0; kk < 8; kk++) {
        asm volatile("cp.async.wait_group 1;" ::: "memory");
        __syncthreads();
        if (kk + 2 < 8) load_chunk(kk + 2, (kk + 2) % 3);

        const uint32_t ab = sbase + (kk % 3) * STAGE_BYTES;
#pragma unroll
        for (int ks = 0; ks < 2; ks++) {
            uint32_t af[2][4];
#pragma unroll
            for (int mt = 0; mt < 2; mt++) {
                int row = wm * 32 + mt * 16 + (lane & 15);
                int col = ks * 16 + (lane >> 4) * 8;
                ldsm_x4(ab + (uint32_t)(row * PADK + col) * 2, af[mt]);
            }
#pragma unroll
            for (int q = 0; q < 4; q++) {
                int rowB = wn * 64 + q * 16 + (lane & 7) + ((lane >> 4) & 1) * 8;
                int colB = ((lane >> 3) & 1) * 8 + ks * 16;
                uint32_t bf[4];
                ldsm_x4(ab + 10240 + (uint32_t)(rowB * PADK + colB) * 2, bf);
#pragma unroll
                for (int mt = 0; mt < 2; mt++) {
                    mma_f16(acc[mt][2 * q + 0], af[mt], bf + 0);
                    mma_f16(acc[mt][2 * q + 1], af[mt], bf + 2);
                }
            }
        }
    }

#pragma unroll
    for (int mt = 0; mt < 2; mt++) {
        int r0 = bm + wm * 32 + mt * 16 + (lane >> 2);
        int r1 = r0 + 8;
#pragma unroll
        for (int nt = 0; nt < 8; nt++) {
            int c = coloff + wn * 64 + nt * 8 + 2 * (lane & 3);
            float bb0 = bp[c], bb1 = bp[c + 1];
            if (halfOut) {
                if (r0 < M)
                    *(__half2*)&C0h[(size_t)r0 * 256 + c] =
                        __floats2half2_rn(acc[mt][nt][0] + bb0, acc[mt][nt][1] + bb1);
                if (r1 < M)
                    *(__half2*)&C0h[(size_t)r1 * 256 + c] =
                        __floats2half2_rn(acc[mt][nt][2] + bb0, acc[mt][nt][3] + bb1);
            } else {
                if (r0 < M) {
                    float2 v = make_float2(acc[mt][nt][0] + bb0, acc[mt][nt][1] + bb1);
                    *(float2*)&Cp[(size_t)r0 * stride + c] = v;
                }
                if (r1 < M) {
                    float2 v = make_float2(acc[mt][nt][2] + bb0, acc[mt][nt][3] + bb1);
                    *(float2*)&Cp[(size_t)r1 * stride + c] = v;
                }
            }
        }
    }
}

// ---------------------------------------------------------------------------
// Deformable sampling: block = 1 query, value fp16.
// Prep (128 thr = head x point): softmax + bilinear -> packed (addr, w) smem.
// Gather (warp = head): lane = (corner = lane>>3, 4 channels = (lane&7)*4);
// one LDG.64 per point, packed LDS.64 for (addr, w). Emits fp16 A for GEMM2.
// ---------------------------------------------------------------------------
__global__ __launch_bounds__(256) void sample_kernel(
    const __half* __restrict__ value,
    const float* __restrict__ off,
    const float* __restrict__ logits,
    const float* __restrict__ ref,
    __half* __restrict__ outA)
{
    const unsigned FULL = 0xffffffffu;
    __shared__ float2 s_aw[HEADS * 16 * 4];   // (addr_as_float, weight)

    const int qg  = blockIdx.x;
    const int n   = qg / LQ;
    const int tid = threadIdx.x;

    if (tid < 128) {
        const int h = tid >> 4;
        const int p = tid & 15;
        const int l = p >> 2;

        float lg = logits[(size_t)qg * 128 + h * 16 + p];
        float mx = lg;
#pragma unroll
        for (int o = 8; o > 0; o >>= 1) mx = fmaxf(mx, __shfl_xor_sync(FULL, mx, o));
        float e = __expf(lg - mx);
        float sum = e;
#pragma unroll
        for (int o = 8; o > 0; o >>= 1) sum += __shfl_xor_sync(FULL, sum, o);
        const float aw = __fdividef(e, sum);

        const int W  = 96 >> l;
        const int S0 = 12288 - 3 * (4096 >> (2 * l));
        const float rx = ref[(size_t)qg * (LEVELS * 2) + l * 2 + 0] * (float)W;
        const float ry = ref[(size_t)qg * (LEVELS * 2) + l * 2 + 1] * (float)W;
        const float ox = off[(size_t)qg * DIM + h * 32 + p * 2 + 0];
        const float oy = off[(size_t)qg * DIM + h * 32 + p * 2 + 1];
        const float x = rx + ox - 0.5f;
        const float y = ry + oy - 0.5f;
        const float x0f = floorf(x), y0f = floorf(y);
        const int x0 = (int)x0f, y0 = (int)y0f;
        const float fx = x - x0f, fy = y - y0f;

        const float vx0 = (x0 >= 0 && x0 < W) ? 1.f : 0.f;
        const float vx1 = (x0 + 1 >= 0 && x0 + 1 < W) ? 1.f : 0.f;
        const float vy0 = (y0 >= 0 && y0 < W) ? 1.f : 0.f;
        const float vy1 = (y0 + 1 >= 0 && y0 + 1 < W) ? 1.f : 0.f;
        const float wx0 = (1.f - fx) * vx0;
        const float wx1 = fx * vx1;
        const float wy0 = (1.f - fy) * aw * vy0;
        const float wy1 = fy * aw * vy1;
        const int c0 = min(max(x0, 0), W - 1) * DIM;
        const int c1 = min(max(x0 + 1, 0), W - 1) * DIM;
        const int r0 = (S0 + min(max(y0, 0), W - 1) * W) * DIM;
        const int r1 = (S0 + min(max(y0 + 1, 0), W - 1) * W) * DIM;

        const int b = tid * 4;
        s_aw[b + 0] = make_float2(__int_as_float(r0 + c0), wx0 * wy0);
        s_aw[b + 1] = make_float2(__int_as_float(r0 + c1), wx1 * wy0);
        s_aw[b + 2] = make_float2(__int_as_float(r1 + c0), wx0 * wy1);
        s_aw[b + 3] = make_float2(__int_as_float(r1 + c1), wx1 * wy1);
    }
    __syncthreads();

    const int h    = tid >> 5;
    const int lane = tid & 31;
    const int c    = lane >> 3;        // corner 0..3
    const int ch   = (lane & 7) * 4;   // channel base 0..28

    const __half* vb = value + (size_t)n * (LQ * DIM) + h * 32 + ch;
    float4 acc = make_float4(0.f, 0.f, 0.f, 0.f);
#pragma unroll
    for (int p = 0; p < 16; p++) {
        const float2 t = s_aw[(h * 16 + p) * 4 + c];
        const int a = __float_as_int(t.x);
        const float w = t.y;
        const uint2 raw = *(const uint2*)(vb + a);
        const float2 v0 = __half22float2(*(const __half2*)&raw.x);
        const float2 v1 = __half22float2(*(const __half2*)&raw.y);
        acc.x = fmaf(w, v0.x, acc.x);
        acc.y = fmaf(w, v0.y, acc.y);
        acc.z = fmaf(w, v1.x, acc.z);
        acc.w = fmaf(w, v1.y, acc.w);
    }
#pragma unroll
    for (int o = 8; o <= 16; o <<= 1) {
        acc.x += __shfl_xor_sync(FULL, acc.x, o);
        acc.y += __shfl_xor_sync(FULL, acc.y, o);
        acc.z += __shfl_xor_sync(FULL, acc.z, o);
        acc.w += __shfl_xor_sync(FULL, acc.w, o);
    }
    if (lane < 8) {
        __half2 p0 = __floats2half2_rn(acc.x, acc.y);
        __half2 p1 = __floats2half2_rn(acc.z, acc.w);
        uint2 v;
        v.x = *(uint32_t*)&p0;
        v.y = *(uint32_t*)&p1;
        *(uint2*)(outA + (size_t)qg * DIM + h * 32 + ch) = v;
    }
}

// ---------------------------------------------------------------------------
// Residual + LayerNorm
// ---------------------------------------------------------------------------
__global__ __launch_bounds__(256) void ln_kernel(
    const float* __restrict__ src, const float* __restrict__ y,
    const float* __restrict__ gamma, const float* __restrict__ beta,
    float* __restrict__ out)
{
    const int row = blockIdx.x;
    const int t = threadIdx.x;
    const size_t idx = (size_t)row * DIM + t;
    const float x = src[idx] + y[idx];

    float s = x, s2 = x * x;
#pragma unroll
    for (int o = 16; o > 0; o >>= 1) {
        s  += __shfl_down_sync(0xffffffffu, s, o);
        s2 += __shfl_down_sync(0xffffffffu, s2, o);
    }
    __shared__ float ss[8], ss2[8];
    const int w = t >> 5;
    if ((t & 31) == 0) { ss[w] = s; ss2[w] = s2; }
    __syncthreads();
    float sum = 0.f, sum2 = 0.f;
#pragma unroll
    for (int i = 0; i < 8; i++) { sum += ss[i]; sum2 += ss2[i]; }

    const float mu  = sum * (1.0f / DIM);
    const float var = sum2 * (1.0f / DIM) - mu * mu;
    const float r = rsqrtf(var + 1e-5f);
    out[idx] = (x - mu) * r * gamma[t] + beta[t];
}

// ---------------------------------------------------------------------------
extern "C" void kernel_launch(void* const* d_in, const int* in_sizes, int n_in,
                              void* d_out, int out_size)
{
    const float* src    = (const float*)d_in[0];
    const float* refpts = (const float*)d_in[1];
    const float* w_value = (const float*)d_in[4];
    const float* b_value = (const float*)d_in[5];
    const float* w_off   = (const float*)d_in[6];
    const float* b_off   = (const float*)d_in[7];
    const float* w_attn  = (const float*)d_in[8];
    const float* b_attn  = (const float*)d_in[9];
    const float* w_out   = (const float*)d_in[10];
    const float* b_out   = (const float*)d_in[11];
    const float* gamma   = (const float*)d_in[12];
    const float* beta    = (const float*)d_in[13];
    float* out = (float*)d_out;

    float *go, *ga, *g2;
    __half *gvh, *af, *bt;
    cudaGetSymbolAddress((void**)&gvh, g_value_h);
    cudaGetSymbolAddress((void**)&go,  g_off);
    cudaGetSymbolAddress((void**)&ga,  g_attn);
    cudaGetSymbolAddress((void**)&g2,  g_out2);
    cudaGetSymbolAddress((void**)&af,  g_af);
    cudaGetSymbolAddress((void**)&bt,  g_btc);

    const int M = MROWS;
    cudaFuncSetAttribute(gemm_mma_kernel, cudaFuncAttributeMaxDynamicSharedMemorySize, SMEM_BYTES);

    dim3 blk(256);
    const int n4 = M * DIM / 4;
    const int gtiles = (M + 127) / 128;   // 192

    // fused weight transpose + src -> fp16
    split_all_kernel<<<896 + (n4 + 255) / 256, blk>>>(
        src, af, n4, w_value, w_off, w_attn, w_out, bt);

    // fused input projections: N=640 (value 256 fp16 | off 256 | attn 128)
    gemm_mma_kernel<<<dim3(gtiles, 5), blk, SMEM_BYTES>>>(
        af, bt, nullptr, gvh, go, ga, b_value, b_off, b_attn, M, 1);

    // deformable sampling (fp16 value; emits fp16 A into af)
    sample_kernel<<<MROWS, blk>>>(gvh, go, ga, refpts, af);

    // output projection
    gemm_mma_kernel<<<dim3(gtiles, 2), blk, SMEM_BYTES>>>(
        af, bt + 640 * 256, g2, nullptr, nullptr, nullptr,
        b_out, nullptr, nullptr, M, 0);

    // residual + layernorm
    ln_kernel<<<MROWS, blk>>>(src, g2, gamma, beta, out);
}

// round 9
// speedup vs baseline: 3.4361x; 1.0378x over previous
#include <cuda_runtime.h>
#include <cuda_fp16.h>
#include <cstdint>
#include <math.h>

#define NB      2
#define LQ      12240
#define DIM     256
#define HEADS   8
#define LEVELS  4
#define POINTS  4
#define HD      32
#define MROWS   (NB * LQ)   // 24480

// ------------------------- scratch (no allocs allowed) ----------------------
// value in HEAD-MAJOR layout: [head][row][32 ch] fp16
__device__ __half g_value_h[HEADS * MROWS * HD];
__device__ float  g_off    [MROWS * DIM];
__device__ float  g_attn   [MROWS * HEADS * 16];
__device__ float  g_out2   [MROWS * DIM];

// fp16 A operand (src, then attention output) and concatenated transposed
// weights [n][k] K-major: rows 0-255 value, 256-511 off, 512-639 attn, 640-895 out
__device__ __half g_af [MROWS * DIM];
__device__ __half g_btc[896 * 256];

// ------------------------------ PTX helpers ---------------------------------
__device__ __forceinline__ uint32_t smem_u32(const void* p) {
    uint32_t a;
    asm("{ .reg .u64 t; cvta.to.shared.u64 t, %1; cvt.u32.u64 %0, t; }" : "=r"(a) : "l"(p));
    return a;
}
__device__ __forceinline__ void cpa16(uint32_t dst, const void* src, bool v) {
    asm volatile("cp.async.cg.shared.global [%0], [%1], 16, %2;"
        :: "r"(dst), "l"(src), "r"(v ? 16 : 0) : "memory");
}
__device__ __forceinline__ void ldsm_x4(uint32_t addr, uint32_t* r) {
    asm volatile("ldmatrix.sync.aligned.m8n8.x4.shared.b16 {%0,%1,%2,%3}, [%4];"
        : "=r"(r[0]), "=r"(r[1]), "=r"(r[2]), "=r"(r[3]) : "r"(addr));
}
__device__ __forceinline__ void mma_f16(float* c, const uint32_t* a, const uint32_t* b) {
    asm volatile("mma.sync.aligned.m16n8k16.row.col.f32.f16.f16.f32 "
        "{%0,%1,%2,%3}, {%4,%5,%6,%7}, {%8,%9}, {%0,%1,%2,%3};"
        : "+f"(c[0]), "+f"(c[1]), "+f"(c[2]), "+f"(c[3])
        : "r"(a[0]), "r"(a[1]), "r"(a[2]), "r"(a[3]), "r"(b[0]), "r"(b[1]));
}

// ---------------------------------------------------------------------------
// Fused split kernel: blocks [0,896) -> weight transpose to fp16,
// blocks [896,...) -> src to fp16.
// ---------------------------------------------------------------------------
__global__ __launch_bounds__(256) void split_all_kernel(
    const float* __restrict__ A, __half* __restrict__ Af, int n4,
    const float* __restrict__ wv, const float* __restrict__ wo,
    const float* __restrict__ wa, const float* __restrict__ ww,
    __half* __restrict__ Bt)
{
    const int bid = blockIdx.x;
    if (bid < 896) {
        int idx = bid * 256 + threadIdx.x;
        int nout = idx >> 8;
        int k = idx & 255;
        const float* src; int nloc, Nc;
        if (nout < 256)      { src = wv; nloc = nout;       Nc = 256; }
        else if (nout < 512) { src = wo; nloc = nout - 256; Nc = 256; }
        else if (nout < 640) { src = wa; nloc = nout - 512; Nc = 128; }
        else                 { src = ww; nloc = nout - 640; Nc = 256; }
        Bt[idx] = __float2half_rn(src[k * Nc + nloc]);
    } else {
        int i = (bid - 896) * 256 + threadIdx.x;
        if (i >= n4) return;
        float4 a = ((const float4*)A)[i];
        __half2 p0 = __floats2half2_rn(a.x, a.y);
        __half2 p1 = __floats2half2_rn(a.z, a.w);
        uint2 v;
        v.x = *(uint32_t*)&p0;
        v.y = *(uint32_t*)&p1;
        *(uint2*)(Af + 4 * (size_t)i) = v;
    }
}

// ---------------------------------------------------------------------------
// fp16 tensor-core GEMM via mma.sync, 3-stage cp.async pipeline.
// CTA tile 128x128, K=256 (8 chunks of 32). 8 warps = 4(M) x 2(N), warp 32x64.
// fused=1: blockIdx.y 0-1 -> value (fp16, HEAD-MAJOR out), 2-3 -> off, 4 -> attn
// ---------------------------------------------------------------------------
#define PADK 40
#define STAGE_BYTES 20480     // A 10240 + B 10240
#define SMEM_BYTES (3 * STAGE_BYTES)

__global__ __launch_bounds__(256) void gemm_mma_kernel(
    const __half* __restrict__ Af, const __half* __restrict__ Bt,
    float* C0, __half* C0h, float* C1, float* C2,
    const float* b0, const float* b1, const float* b2,
    int M, int fused)
{
    extern __shared__ __align__(16) char smem[];
    const uint32_t sbase = smem_u32(smem);

    const int tid  = threadIdx.x;
    const int lane = tid & 31;
    const int wid  = tid >> 5;
    const int wm   = wid & 3;
    const int wn   = wid >> 2;
    const int bm   = blockIdx.x * 128;
    const int bn   = blockIdx.y * 128;

    float* Cp; const float* bp; int stride, coloff; bool halfOut = false;
    if (fused) {
        if (blockIdx.y < 2)      { Cp = C0; bp = b0; stride = 256; coloff = bn; halfOut = true; }
        else if (blockIdx.y < 4) { Cp = C1; bp = b1; stride = 256; coloff = bn - 256; }
        else                     { Cp = C2; bp = b2; stride = 128; coloff = 0; }
    } else { Cp = C0; bp = b0; stride = 256; coloff = bn; }

    float acc[2][8][4];
#pragma unroll
    for (int i = 0; i < 2; i++)
#pragma unroll
        for (int j = 0; j < 8; j++)
#pragma unroll
            for (int t = 0; t < 4; t++) acc[i][j][t] = 0.f;

    auto load_chunk = [&](int kk, int st) {
        const uint32_t base = sbase + st * STAGE_BYTES;
#pragma unroll
        for (int t = 0; t < 2; t++) {
            int idx = tid + 256 * t;
            int row = idx >> 2, seg = idx & 3;
            uint32_t d = (uint32_t)(row * PADK + seg * 8) * 2;
            bool va = (bm + row) < M;
            cpa16(base + d, Af + (size_t)(bm + row) * 256 + kk * 32 + seg * 8, va);
            cpa16(base + 10240 + d, Bt + (size_t)(bn + row) * 256 + kk * 32 + seg * 8, true);
        }
        asm volatile("cp.async.commit_group;" ::: "memory");
    };

    load_chunk(0, 0);
    load_chunk(1, 1);

    for (int kk = 0; kk < 8; kk++) {
        asm volatile("cp.async.wait_group 1;" ::: "memory");
        __syncthreads();
        if (kk + 2 < 8) load_chunk(kk + 2, (kk + 2) % 3);

        const uint32_t ab = sbase + (kk % 3) * STAGE_BYTES;
#pragma unroll
        for (int ks = 0; ks < 2; ks++) {
            uint32_t af[2][4];
#pragma unroll
            for (int mt = 0; mt < 2; mt++) {
                int row = wm * 32 + mt * 16 + (lane & 15);
                int col = ks * 16 + (lane >> 4) * 8;
                ldsm_x4(ab + (uint32_t)(row * PADK + col) * 2, af[mt]);
            }
#pragma unroll
            for (int q = 0; q < 4; q++) {
                int rowB = wn * 64 + q * 16 + (lane & 7) + ((lane >> 4) & 1) * 8;
                int colB = ((lane >> 3) & 1) * 8 + ks * 16;
                uint32_t bf[4];
                ldsm_x4(ab + 10240 + (uint32_t)(rowB * PADK + colB) * 2, bf);
#pragma unroll
                for (int mt = 0; mt < 2; mt++) {
                    mma_f16(acc[mt][2 * q + 0], af[mt], bf + 0);
                    mma_f16(acc[mt][2 * q + 1], af[mt], bf + 2);
                }
            }
        }
    }

#pragma unroll
    for (int mt = 0; mt < 2; mt++) {
        int r0 = bm + wm * 32 + mt * 16 + (lane >> 2);
        int r1 = r0 + 8;
#pragma unroll
        for (int nt = 0; nt < 8; nt++) {
            int c = coloff + wn * 64 + nt * 8 + 2 * (lane & 3);
            float bb0 = bp[c], bb1 = bp[c + 1];
            if (halfOut) {
                // head-major value layout: [head][row][32]
                const int h = c >> 5, chm = c & 31;
                __half* basep = C0h + (size_t)h * MROWS * HD + chm;
                if (r0 < M)
                    *(__half2*)(basep + (size_t)r0 * HD) =
                        __floats2half2_rn(acc[mt][nt][0] + bb0, acc[mt][nt][1] + bb1);
                if (r1 < M)
                    *(__half2*)(basep + (size_t)r1 * HD) =
                        __floats2half2_rn(acc[mt][nt][2] + bb0, acc[mt][nt][3] + bb1);
            } else {
                if (r0 < M) {
                    float2 v = make_float2(acc[mt][nt][0] + bb0, acc[mt][nt][1] + bb1);
                    *(float2*)&Cp[(size_t)r0 * stride + c] = v;
                }
                if (r1 < M) {
                    float2 v = make_float2(acc[mt][nt][2] + bb0, acc[mt][nt][3] + bb1);
                    *(float2*)&Cp[(size_t)r1 * stride + c] = v;
                }
            }
        }
    }
}

// ---------------------------------------------------------------------------
// Deformable sampling v4: head-major fp16 value, x-pair gathers.
// Prep (128 thr = head x point): softmax + bilinear; x-corners collapsed to a
// clamped pair base pb (contiguous 128B), slot weights remapped (zeros drop
// invalid positions exactly). smem: 4 (addr, w) slots per point:
//   slot = (ypair<<1)|xslot ; addr = (S0 + y*W + pb)*32 + xslot*32
// Gather (warp = head): lane = (slot = lane>>3, 4 ch = (lane&7)*4); each point
// is one LDG.64/lane; lanes 0-15 cover row y0's 128B pair, 16-31 row y1's.
// ---------------------------------------------------------------------------
__global__ __launch_bounds__(256) void sample_kernel(
    const __half* __restrict__ value,
    const float* __restrict__ off,
    const float* __restrict__ logits,
    const float* __restrict__ ref,
    __half* __restrict__ outA)
{
    const unsigned FULL = 0xffffffffu;
    __shared__ float2 s_aw[HEADS * 16 * 4];   // (addr_as_float, weight)

    const int qg  = blockIdx.x;
    const int n   = qg / LQ;
    const int tid = threadIdx.x;

    if (tid < 128) {
        const int h = tid >> 4;
        const int p = tid & 15;
        const int l = p >> 2;

        float lg = logits[(size_t)qg * 128 + h * 16 + p];
        float mx = lg;
#pragma unroll
        for (int o = 8; o > 0; o >>= 1) mx = fmaxf(mx, __shfl_xor_sync(FULL, mx, o));
        float e = __expf(lg - mx);
        float sum = e;
#pragma unroll
        for (int o = 8; o > 0; o >>= 1) sum += __shfl_xor_sync(FULL, sum, o);
        const float aw = __fdividef(e, sum);

        const int W  = 96 >> l;
        const int S0 = 12288 - 3 * (4096 >> (2 * l));
        const float rx = ref[(size_t)qg * (LEVELS * 2) + l * 2 + 0] * (float)W;
        const float ry = ref[(size_t)qg * (LEVELS * 2) + l * 2 + 1] * (float)W;
        const float ox = off[(size_t)qg * DIM + h * 32 + p * 2 + 0];
        const float oy = off[(size_t)qg * DIM + h * 32 + p * 2 + 1];
        const float x = rx + ox - 0.5f;
        const float y = ry + oy - 0.5f;
        const float x0f = floorf(x), y0f = floorf(y);
        const int x0 = (int)x0f, y0 = (int)y0f;
        const int x1 = x0 + 1, y1 = y0 + 1;
        const float fx = x - x0f, fy = y - y0f;

        // x weights with validity folded in
        const float wx0 = (x0 >= 0 && x0 < W) ? (1.f - fx) : 0.f;
        const float wx1 = (x1 >= 0 && x1 < W) ? fx : 0.f;
        // clamped pair base and slot weight remap (exact: dropped weights are 0)
        const int pb = min(max(x0, 0), W - 2);
        const float wa = (pb == x0) ? wx0 : ((pb == x1) ? wx1 : 0.f);
        const float wb = (pb + 1 == x0) ? wx0 : ((pb + 1 == x1) ? wx1 : 0.f);
        // y weights (include attention weight)
        const float wy0 = ((y0 >= 0 && y0 < W) ? (1.f - fy) : 0.f) * aw;
        const float wy1 = ((y1 >= 0 && y1 < W) ? fy : 0.f) * aw;
        const int y0c = min(max(y0, 0), W - 1);
        const int y1c = min(max(y1, 0), W - 1);
        const int a0 = (S0 + y0c * W + pb) * HD;   // fp16 elements within head-plane
        const int a1 = (S0 + y1c * W + pb) * HD;

        const int b = tid * 4;
        s_aw[b + 0] = make_float2(__int_as_float(a0),      wa * wy0);
        s_aw[b + 1] = make_float2(__int_as_float(a0 + HD), wb * wy0);
        s_aw[b + 2] = make_float2(__int_as_float(a1),      wa * wy1);
        s_aw[b + 3] = make_float2(__int_as_float(a1 + HD), wb * wy1);
    }
    __syncthreads();

    const int h    = tid >> 5;
    const int lane = tid & 31;
    const int slot = lane >> 3;        // (ypair<<1)|xslot
    const int ch   = (lane & 7) * 4;   // channel base 0..28

    const __half* vb = value + ((size_t)h * MROWS + (size_t)n * LQ) * HD + ch;
    float4 acc = make_float4(0.f, 0.f, 0.f, 0.f);
#pragma unroll
    for (int p = 0; p < 16; p++) {
        const float2 t = s_aw[(h * 16 + p) * 4 + slot];
        const int a = __float_as_int(t.x);
        const float w = t.y;
        const uint2 raw = *(const uint2*)(vb + a);
        const float2 v0 = __half22float2(*(const __half2*)&raw.x);
        const float2 v1 = __half22float2(*(const __half2*)&raw.y);
        acc.x = fmaf(w, v0.x, acc.x);
        acc.y = fmaf(w, v0.y, acc.y);
        acc.z = fmaf(w, v1.x, acc.z);
        acc.w = fmaf(w, v1.y, acc.w);
    }
#pragma unroll
    for (int o = 8; o <= 16; o <<= 1) {
        acc.x += __shfl_xor_sync(FULL, acc.x, o);
        acc.y += __shfl_xor_sync(FULL, acc.y, o);
        acc.z += __shfl_xor_sync(FULL, acc.z, o);
        acc.w += __shfl_xor_sync(FULL, acc.w, o);
    }
    if (lane < 8) {
        __half2 p0 = __floats2half2_rn(acc.x, acc.y);
        __half2 p1 = __floats2half2_rn(acc.z, acc.w);
        uint2 v;
        v.x = *(uint32_t*)&p0;
        v.y = *(uint32_t*)&p1;
        *(uint2*)(outA + (size_t)qg * DIM + h * 32 + ch) = v;
    }
}

// ---------------------------------------------------------------------------
// Residual + LayerNorm
// ---------------------------------------------------------------------------
__global__ __launch_bounds__(256) void ln_kernel(
    const float* __restrict__ src, const float* __restrict__ y,
    const float* __restrict__ gamma, const float* __restrict__ beta,
    float* __restrict__ out)
{
    const int row = blockIdx.x;
    const int t = threadIdx.x;
    const size_t idx = (size_t)row * DIM + t;
    const float x = src[idx] + y[idx];

    float s = x, s2 = x * x;
#pragma unroll
    for (int o = 16; o > 0; o >>= 1) {
        s  += __shfl_down_sync(0xffffffffu, s, o);
        s2 += __shfl_down_sync(0xffffffffu, s2, o);
    }
    __shared__ float ss[8], ss2[8];
    const int w = t >> 5;
    if ((t & 31) == 0) { ss[w] = s; ss2[w] = s2; }
    __syncthreads();
    float sum = 0.f, sum2 = 0.f;
#pragma unroll
    for (int i = 0; i < 8; i++) { sum += ss[i]; sum2 += ss2[i]; }

    const float mu  = sum * (1.0f / DIM);
    const float var = sum2 * (1.0f / DIM) - mu * mu;
    const float r = rsqrtf(var + 1e-5f);
    out[idx] = (x - mu) * r * gamma[t] + beta[t];
}

// ---------------------------------------------------------------------------
extern "C" void kernel_launch(void* const* d_in, const int* in_sizes, int n_in,
                              void* d_out, int out_size)
{
    const float* src    = (const float*)d_in[0];
    const float* refpts = (const float*)d_in[1];
    const float* w_value = (const float*)d_in[4];
    const float* b_value = (const float*)d_in[5];
    const float* w_off   = (const float*)d_in[6];
    const float* b_off   = (const float*)d_in[7];
    const float* w_attn  = (const float*)d_in[8];
    const float* b_attn  = (const float*)d_in[9];
    const float* w_out   = (const float*)d_in[10];
    const float* b_out   = (const float*)d_in[11];
    const float* gamma   = (const float*)d_in[12];
    const float* beta    = (const float*)d_in[13];
    float* out = (float*)d_out;

    float *go, *ga, *g2;
    __half *gvh, *af, *bt;
    cudaGetSymbolAddress((void**)&gvh, g_value_h);
    cudaGetSymbolAddress((void**)&go,  g_off);
    cudaGetSymbolAddress((void**)&ga,  g_attn);
    cudaGetSymbolAddress((void**)&g2,  g_out2);
    cudaGetSymbolAddress((void**)&af,  g_af);
    cudaGetSymbolAddress((void**)&bt,  g_btc);

    const int M = MROWS;
    cudaFuncSetAttribute(gemm_mma_kernel, cudaFuncAttributeMaxDynamicSharedMemorySize, SMEM_BYTES);

    dim3 blk(256);
    const int n4 = M * DIM / 4;
    const int gtiles = (M + 127) / 128;   // 192

    // fused weight transpose + src -> fp16
    split_all_kernel<<<896 + (n4 + 255) / 256, blk>>>(
        src, af, n4, w_value, w_off, w_attn, w_out, bt);

    // fused input projections: N=640 (value 256 fp16 head-major | off 256 | attn 128)
    gemm_mma_kernel<<<dim3(gtiles, 5), blk, SMEM_BYTES>>>(
        af, bt, nullptr, gvh, go, ga, b_value, b_off, b_attn, M, 1);

    // deformable sampling (head-major fp16 value; emits fp16 A into af)
    sample_kernel<<<MROWS, blk>>>(gvh, go, ga, refpts, af);

    // output projection
    gemm_mma_kernel<<<dim3(gtiles, 2), blk, SMEM_BYTES>>>(
        af, bt + 640 * 256, g2, nullptr, nullptr, nullptr,
        b_out, nullptr, nullptr, M, 0);

    // residual + layernorm
    ln_kernel<<<MROWS, blk>>>(src, g2, gamma, beta, out);
}

// round 10
// speedup vs baseline: 3.4884x; 1.0152x over previous
#include <cuda_runtime.h>
#include <cuda_fp16.h>
#include <cstdint>
#include <math.h>

#define NB      2
#define LQ      12240
#define DIM     256
#define HEADS   8
#define LEVELS  4
#define POINTS  4
#define HD      32
#define MROWS   (NB * LQ)   // 24480

// ------------------------- scratch (no allocs allowed) ----------------------
// value in HEAD-MAJOR layout: [head][row][32 ch] fp16
__device__ __half g_value_h[HEADS * MROWS * HD];
__device__ float  g_off    [MROWS * DIM];
__device__ float  g_attn   [MROWS * HEADS * 16];
__device__ float  g_out2   [MROWS * DIM];

// fp16 A operand (src, then attention output) and concatenated transposed
// weights [n][k] K-major: rows 0-255 value, 256-511 off, 512-639 attn, 640-895 out
__device__ __half g_af [MROWS * DIM];
__device__ __half g_btc[896 * 256];

// ------------------------------ PTX helpers ---------------------------------
__device__ __forceinline__ uint32_t smem_u32(const void* p) {
    uint32_t a;
    asm("{ .reg .u64 t; cvta.to.shared.u64 t, %1; cvt.u32.u64 %0, t; }" : "=r"(a) : "l"(p));
    return a;
}
__device__ __forceinline__ void cpa16(uint32_t dst, const void* src, bool v) {
    asm volatile("cp.async.cg.shared.global [%0], [%1], 16, %2;"
        :: "r"(dst), "l"(src), "r"(v ? 16 : 0) : "memory");
}
__device__ __forceinline__ void ldsm_x4(uint32_t addr, uint32_t* r) {
    asm volatile("ldmatrix.sync.aligned.m8n8.x4.shared.b16 {%0,%1,%2,%3}, [%4];"
        : "=r"(r[0]), "=r"(r[1]), "=r"(r[2]), "=r"(r[3]) : "r"(addr));
}
__device__ __forceinline__ void mma_f16(float* c, const uint32_t* a, const uint32_t* b) {
    asm volatile("mma.sync.aligned.m16n8k16.row.col.f32.f16.f16.f32 "
        "{%0,%1,%2,%3}, {%4,%5,%6,%7}, {%8,%9}, {%0,%1,%2,%3};"
        : "+f"(c[0]), "+f"(c[1]), "+f"(c[2]), "+f"(c[3])
        : "r"(a[0]), "r"(a[1]), "r"(a[2]), "r"(a[3]), "r"(b[0]), "r"(b[1]));
}

// ---------------------------------------------------------------------------
// Fused split kernel: blocks [0,896) -> weight transpose to fp16,
// blocks [896,...) -> src to fp16.
// ---------------------------------------------------------------------------
__global__ __launch_bounds__(256) void split_all_kernel(
    const float* __restrict__ A, __half* __restrict__ Af, int n4,
    const float* __restrict__ wv, const float* __restrict__ wo,
    const float* __restrict__ wa, const float* __restrict__ ww,
    __half* __restrict__ Bt)
{
    const int bid = blockIdx.x;
    if (bid < 896) {
        int idx = bid * 256 + threadIdx.x;
        int nout = idx >> 8;
        int k = idx & 255;
        const float* src; int nloc, Nc;
        if (nout < 256)      { src = wv; nloc = nout;       Nc = 256; }
        else if (nout < 512) { src = wo; nloc = nout - 256; Nc = 256; }
        else if (nout < 640) { src = wa; nloc = nout - 512; Nc = 128; }
        else                 { src = ww; nloc = nout - 640; Nc = 256; }
        Bt[idx] = __float2half_rn(src[k * Nc + nloc]);
    } else {
        int i = (bid - 896) * 256 + threadIdx.x;
        if (i >= n4) return;
        float4 a = ((const float4*)A)[i];
        __half2 p0 = __floats2half2_rn(a.x, a.y);
        __half2 p1 = __floats2half2_rn(a.z, a.w);
        uint2 v;
        v.x = *(uint32_t*)&p0;
        v.y = *(uint32_t*)&p1;
        *(uint2*)(Af + 4 * (size_t)i) = v;
    }
}

// ---------------------------------------------------------------------------
// fp16 tensor-core GEMM via mma.sync, 3-stage cp.async pipeline.
// CTA tile 128x128, K=256 (8 chunks of 32). 8 warps = 4(M) x 2(N), warp 32x64.
// Per chunk: ALL 12 ldmatrix first (both k16 halves), then 32 back-to-back
// HMMAs -> LDS latency paid once per chunk instead of per q-group.
// fused=1: blockIdx.y 0-1 -> value (fp16, HEAD-MAJOR out), 2-3 -> off, 4 -> attn
// ---------------------------------------------------------------------------
#define PADK 40
#define STAGE_BYTES 20480     // A 10240 + B 10240
#define SMEM_BYTES (3 * STAGE_BYTES)

__global__ __launch_bounds__(256, 2) void gemm_mma_kernel(
    const __half* __restrict__ Af, const __half* __restrict__ Bt,
    float* C0, __half* C0h, float* C1, float* C2,
    const float* b0, const float* b1, const float* b2,
    int M, int fused)
{
    extern __shared__ __align__(16) char smem[];
    const uint32_t sbase = smem_u32(smem);

    const int tid  = threadIdx.x;
    const int lane = tid & 31;
    const int wid  = tid >> 5;
    const int wm   = wid & 3;
    const int wn   = wid >> 2;
    const int bm   = blockIdx.x * 128;
    const int bn   = blockIdx.y * 128;

    float* Cp; const float* bp; int stride, coloff; bool halfOut = false;
    if (fused) {
        if (blockIdx.y < 2)      { Cp = C0; bp = b0; stride = 256; coloff = bn; halfOut = true; }
        else if (blockIdx.y < 4) { Cp = C1; bp = b1; stride = 256; coloff = bn - 256; }
        else                     { Cp = C2; bp = b2; stride = 128; coloff = 0; }
    } else { Cp = C0; bp = b0; stride = 256; coloff = bn; }

    float acc[2][8][4];
#pragma unroll
    for (int i = 0; i < 2; i++)
#pragma unroll
        for (int j = 0; j < 8; j++)
#pragma unroll
            for (int t = 0; t < 4; t++) acc[i][j][t] = 0.f;

    auto load_chunk = [&](int kk, int st) {
        const uint32_t base = sbase + st * STAGE_BYTES;
#pragma unroll
        for (int t = 0; t < 2; t++) {
            int idx = tid + 256 * t;
            int row = idx >> 2, seg = idx & 3;
            uint32_t d = (uint32_t)(row * PADK + seg * 8) * 2;
            bool va = (bm + row) < M;
            cpa16(base + d, Af + (size_t)(bm + row) * 256 + kk * 32 + seg * 8, va);
            cpa16(base + 10240 + d, Bt + (size_t)(bn + row) * 256 + kk * 32 + seg * 8, true);
        }
        asm volatile("cp.async.commit_group;" ::: "memory");
    };

    load_chunk(0, 0);
    load_chunk(1, 1);

    // precomputed intra-tile ldmatrix offsets
    const int arow = wm * 32 + (lane & 15);
    const int acolbase = (lane >> 4) * 8;
    const int browq = wn * 64 + (lane & 7) + ((lane >> 4) & 1) * 8;
    const int bcolbase = ((lane >> 3) & 1) * 8;

    for (int kk = 0; kk < 8; kk++) {
        asm volatile("cp.async.wait_group 1;" ::: "memory");
        __syncthreads();
        if (kk + 2 < 8) load_chunk(kk + 2, (kk + 2) % 3);

        const uint32_t ab = sbase + (kk % 3) * STAGE_BYTES;

        uint32_t Ar[2][2][4];   // [ks][mt][4]
        uint32_t Br[2][4][4];   // [ks][q][4]
#pragma unroll
        for (int ks = 0; ks < 2; ks++) {
#pragma unroll
            for (int mt = 0; mt < 2; mt++) {
                int row = arow + mt * 16;
                int col = ks * 16 + acolbase;
                ldsm_x4(ab + (uint32_t)(row * PADK + col) * 2, Ar[ks][mt]);
            }
#pragma unroll
            for (int q = 0; q < 4; q++) {
                int rowB = browq + q * 16;
                int colB = bcolbase + ks * 16;
                ldsm_x4(ab + 10240 + (uint32_t)(rowB * PADK + colB) * 2, Br[ks][q]);
            }
        }
#pragma unroll
        for (int ks = 0; ks < 2; ks++)
#pragma unroll
            for (int q = 0; q < 4; q++)
#pragma unroll
                for (int mt = 0; mt < 2; mt++) {
                    mma_f16(acc[mt][2 * q + 0], Ar[ks][mt], Br[ks][q] + 0);
                    mma_f16(acc[mt][2 * q + 1], Ar[ks][mt], Br[ks][q] + 2);
                }
    }

#pragma unroll
    for (int mt = 0; mt < 2; mt++) {
        int r0 = bm + wm * 32 + mt * 16 + (lane >> 2);
        int r1 = r0 + 8;
#pragma unroll
        for (int nt = 0; nt < 8; nt++) {
            int c = coloff + wn * 64 + nt * 8 + 2 * (lane & 3);
            float bb0 = bp[c], bb1 = bp[c + 1];
            if (halfOut) {
                // head-major value layout: [head][row][32]
                const int h = c >> 5, chm = c & 31;
                __half* basep = C0h + (size_t)h * MROWS * HD + chm;
                if (r0 < M)
                    *(__half2*)(basep + (size_t)r0 * HD) =
                        __floats2half2_rn(acc[mt][nt][0] + bb0, acc[mt][nt][1] + bb1);
                if (r1 < M)
                    *(__half2*)(basep + (size_t)r1 * HD) =
                        __floats2half2_rn(acc[mt][nt][2] + bb0, acc[mt][nt][3] + bb1);
            } else {
                if (r0 < M) {
                    float2 v = make_float2(acc[mt][nt][0] + bb0, acc[mt][nt][1] + bb1);
                    *(float2*)&Cp[(size_t)r0 * stride + c] = v;
                }
                if (r1 < M) {
                    float2 v = make_float2(acc[mt][nt][2] + bb0, acc[mt][nt][3] + bb1);
                    *(float2*)&Cp[(size_t)r1 * stride + c] = v;
                }
            }
        }
    }
}

// ---------------------------------------------------------------------------
// Deformable sampling: head-major fp16 value, x-pair gathers.
// ---------------------------------------------------------------------------
__global__ __launch_bounds__(256) void sample_kernel(
    const __half* __restrict__ value,
    const float* __restrict__ off,
    const float* __restrict__ logits,
    const float* __restrict__ ref,
    __half* __restrict__ outA)
{
    const unsigned FULL = 0xffffffffu;
    __shared__ float2 s_aw[HEADS * 16 * 4];   // (addr_as_float, weight)

    const int qg  = blockIdx.x;
    const int n   = qg / LQ;
    const int tid = threadIdx.x;

    if (tid < 128) {
        const int h = tid >> 4;
        const int p = tid & 15;
        const int l = p >> 2;

        float lg = logits[(size_t)qg * 128 + h * 16 + p];
        float mx = lg;
#pragma unroll
        for (int o = 8; o > 0; o >>= 1) mx = fmaxf(mx, __shfl_xor_sync(FULL, mx, o));
        float e = __expf(lg - mx);
        float sum = e;
#pragma unroll
        for (int o = 8; o > 0; o >>= 1) sum += __shfl_xor_sync(FULL, sum, o);
        const float aw = __fdividef(e, sum);

        const int W  = 96 >> l;
        const int S0 = 12288 - 3 * (4096 >> (2 * l));
        const float rx = ref[(size_t)qg * (LEVELS * 2) + l * 2 + 0] * (float)W;
        const float ry = ref[(size_t)qg * (LEVELS * 2) + l * 2 + 1] * (float)W;
        const float ox = off[(size_t)qg * DIM + h * 32 + p * 2 + 0];
        const float oy = off[(size_t)qg * DIM + h * 32 + p * 2 + 1];
        const float x = rx + ox - 0.5f;
        const float y = ry + oy - 0.5f;
        const float x0f = floorf(x), y0f = floorf(y);
        const int x0 = (int)x0f, y0 = (int)y0f;
        const int x1 = x0 + 1, y1 = y0 + 1;
        const float fx = x - x0f, fy = y - y0f;

        const float wx0 = (x0 >= 0 && x0 < W) ? (1.f - fx) : 0.f;
        const float wx1 = (x1 >= 0 && x1 < W) ? fx : 0.f;
        const int pb = min(max(x0, 0), W - 2);
        const float wa = (pb == x0) ? wx0 : ((pb == x1) ? wx1 : 0.f);
        const float wb = (pb + 1 == x0) ? wx0 : ((pb + 1 == x1) ? wx1 : 0.f);
        const float wy0 = ((y0 >= 0 && y0 < W) ? (1.f - fy) : 0.f) * aw;
        const float wy1 = ((y1 >= 0 && y1 < W) ? fy : 0.f) * aw;
        const int y0c = min(max(y0, 0), W - 1);
        const int y1c = min(max(y1, 0), W - 1);
        const int a0 = (S0 + y0c * W + pb) * HD;
        const int a1 = (S0 + y1c * W + pb) * HD;

        const int b = tid * 4;
        s_aw[b + 0] = make_float2(__int_as_float(a0),      wa * wy0);
        s_aw[b + 1] = make_float2(__int_as_float(a0 + HD), wb * wy0);
        s_aw[b + 2] = make_float2(__int_as_float(a1),      wa * wy1);
        s_aw[b + 3] = make_float2(__int_as_float(a1 + HD), wb * wy1);
    }
    __syncthreads();

    const int h    = tid >> 5;
    const int lane = tid & 31;
    const int slot = lane >> 3;        // (ypair<<1)|xslot
    const int ch   = (lane & 7) * 4;   // channel base 0..28

    const __half* vb = value + ((size_t)h * MROWS + (size_t)n * LQ) * HD + ch;
    float4 acc = make_float4(0.f, 0.f, 0.f, 0.f);
#pragma unroll
    for (int p = 0; p < 16; p++) {
        const float2 t = s_aw[(h * 16 + p) * 4 + slot];
        const int a = __float_as_int(t.x);
        const float w = t.y;
        const uint2 raw = *(const uint2*)(vb + a);
        const float2 v0 = __half22float2(*(const __half2*)&raw.x);
        const float2 v1 = __half22float2(*(const __half2*)&raw.y);
        acc.x = fmaf(w, v0.x, acc.x);
        acc.y = fmaf(w, v0.y, acc.y);
        acc.z = fmaf(w, v1.x, acc.z);
        acc.w = fmaf(w, v1.y, acc.w);
    }
#pragma unroll
    for (int o = 8; o <= 16; o <<= 1) {
        acc.x += __shfl_xor_sync(FULL, acc.x, o);
        acc.y += __shfl_xor_sync(FULL, acc.y, o);
        acc.z += __shfl_xor_sync(FULL, acc.z, o);
        acc.w += __shfl_xor_sync(FULL, acc.w, o);
    }
    if (lane < 8) {
        __half2 p0 = __floats2half2_rn(acc.x, acc.y);
        __half2 p1 = __floats2half2_rn(acc.z, acc.w);
        uint2 v;
        v.x = *(uint32_t*)&p0;
        v.y = *(uint32_t*)&p1;
        *(uint2*)(outA + (size_t)qg * DIM + h * 32 + ch) = v;
    }
}

// ---------------------------------------------------------------------------
// Residual + LayerNorm
// ---------------------------------------------------------------------------
__global__ __launch_bounds__(256) void ln_kernel(
    const float* __restrict__ src, const float* __restrict__ y,
    const float* __restrict__ gamma, const float* __restrict__ beta,
    float* __restrict__ out)
{
    const int row = blockIdx.x;
    const int t = threadIdx.x;
    const size_t idx = (size_t)row * DIM + t;
    const float x = src[idx] + y[idx];

    float s = x, s2 = x * x;
#pragma unroll
    for (int o = 16; o > 0; o >>= 1) {
        s  += __shfl_down_sync(0xffffffffu, s, o);
        s2 += __shfl_down_sync(0xffffffffu, s2, o);
    }
    __shared__ float ss[8], ss2[8];
    const int w = t >> 5;
    if ((t & 31) == 0) { ss[w] = s; ss2[w] = s2; }
    __syncthreads();
    float sum = 0.f, sum2 = 0.f;
#pragma unroll
    for (int i = 0; i < 8; i++) { sum += ss[i]; sum2 += ss2[i]; }

    const float mu  = sum * (1.0f / DIM);
    const float var = sum2 * (1.0f / DIM) - mu * mu;
    const float r = rsqrtf(var + 1e-5f);
    out[idx] = (x - mu) * r * gamma[t] + beta[t];
}

// ---------------------------------------------------------------------------
extern "C" void kernel_launch(void* const* d_in, const int* in_sizes, int n_in,
                              void* d_out, int out_size)
{
    const float* src    = (const float*)d_in[0];
    const float* refpts = (const float*)d_in[1];
    const float* w_value = (const float*)d_in[4];
    const float* b_value = (const float*)d_in[5];
    const float* w_off   = (const float*)d_in[6];
    const float* b_off   = (const float*)d_in[7];
    const float* w_attn  = (const float*)d_in[8];
    const float* b_attn  = (const float*)d_in[9];
    const float* w_out   = (const float*)d_in[10];
    const float* b_out   = (const float*)d_in[11];
    const float* gamma   = (const float*)d_in[12];
    const float* beta    = (const float*)d_in[13];
    float* out = (float*)d_out;

    float *go, *ga, *g2;
    __half *gvh, *af, *bt;
    cudaGetSymbolAddress((void**)&gvh, g_value_h);
    cudaGetSymbolAddress((void**)&go,  g_off);
    cudaGetSymbolAddress((void**)&ga,  g_attn);
    cudaGetSymbolAddress((void**)&g2,  g_out2);
    cudaGetSymbolAddress((void**)&af,  g_af);
    cudaGetSymbolAddress((void**)&bt,  g_btc);

    const int M = MROWS;
    cudaFuncSetAttribute(gemm_mma_kernel, cudaFuncAttributeMaxDynamicSharedMemorySize, SMEM_BYTES);

    dim3 blk(256);
    const int n4 = M * DIM / 4;
    const int gtiles = (M + 127) / 128;   // 192

    // fused weight transpose + src -> fp16
    split_all_kernel<<<896 + (n4 + 255) / 256, blk>>>(
        src, af, n4, w_value, w_off, w_attn, w_out, bt);

    // fused input projections: N=640 (value 256 fp16 head-major | off 256 | attn 128)
    gemm_mma_kernel<<<dim3(gtiles, 5), blk, SMEM_BYTES>>>(
        af, bt, nullptr, gvh, go, ga, b_value, b_off, b_attn, M, 1);

    // deformable sampling (head-major fp16 value; emits fp16 A into af)
    sample_kernel<<<MROWS, blk>>>(gvh, go, ga, refpts, af);

    // output projection
    gemm_mma_kernel<<<dim3(gtiles, 2), blk, SMEM_BYTES>>>(
        af, bt + 640 * 256, g2, nullptr, nullptr, nullptr,
        b_out, nullptr, nullptr, M, 0);

    // residual + layernorm
    ln_kernel<<<MROWS, blk>>>(src, g2, gamma, beta, out);
}